// round 1
// baseline (speedup 1.0000x reference)
#include <cuda_runtime.h>
#include <math.h>
#include <stdint.h>

// Problem constants
#define D_MODEL 1024
#define S_LEN   2048
#define BATCH   2
#define NH      16
#define DK      64
#define DFF     4096
#define MROWS   (BATCH * S_LEN)   // 4096

// ---------------------------------------------------------------------------
// Scratch (device globals — no allocation allowed)
// ---------------------------------------------------------------------------
__device__ float g_xn[(size_t)MROWS * D_MODEL];
__device__ float g_q [(size_t)MROWS * D_MODEL];
__device__ float g_k [(size_t)MROWS * D_MODEL];
__device__ float g_v [(size_t)MROWS * D_MODEL];
__device__ float g_at[(size_t)MROWS * D_MODEL];
__device__ float g_h [(size_t)MROWS * D_MODEL];
__device__ float g_hn[(size_t)MROWS * D_MODEL];
__device__ float g_ff[(size_t)MROWS * DFF];

// ---------------------------------------------------------------------------
// LayerNorm: one block per row, 256 threads, float4
// ---------------------------------------------------------------------------
__device__ __forceinline__ float block_sum_256(float v, float* red) {
    __syncthreads();                       // protect red[] reuse across calls
    #pragma unroll
    for (int o = 16; o; o >>= 1) v += __shfl_xor_sync(0xffffffffu, v, o);
    if ((threadIdx.x & 31) == 0) red[threadIdx.x >> 5] = v;
    __syncthreads();
    if (threadIdx.x < 32) {
        float w = (threadIdx.x < 8) ? red[threadIdx.x] : 0.0f;
        #pragma unroll
        for (int o = 4; o; o >>= 1) w += __shfl_xor_sync(0xffffffffu, w, o);
        if (threadIdx.x == 0) red[0] = w;
    }
    __syncthreads();
    return red[0];
}

__global__ __launch_bounds__(256) void ln_kernel(
    const float* __restrict__ x, const float* __restrict__ g,
    const float* __restrict__ b, float* __restrict__ out)
{
    __shared__ float red[32];
    const int row = blockIdx.x;
    const int t = threadIdx.x;
    const float4* xr = reinterpret_cast<const float4*>(x + (size_t)row * D_MODEL);
    float4 v = xr[t];

    float s = v.x + v.y + v.z + v.w;
    float mu = block_sum_256(s, red) * (1.0f / (float)D_MODEL);

    float dx = v.x - mu, dy = v.y - mu, dz = v.z - mu, dw = v.w - mu;
    float sq = dx * dx + dy * dy + dz * dz + dw * dw;
    float var = block_sum_256(sq, red) * (1.0f / (float)D_MODEL);
    float inv = rsqrtf(var + 1e-5f);

    float4 gg = reinterpret_cast<const float4*>(g)[t];
    float4 bb = reinterpret_cast<const float4*>(b)[t];
    float4 o;
    o.x = dx * inv * gg.x + bb.x;
    o.y = dy * inv * gg.y + bb.y;
    o.z = dz * inv * gg.z + bb.z;
    o.w = dw * inv * gg.w + bb.w;
    reinterpret_cast<float4*>(out + (size_t)row * D_MODEL)[t] = o;
}

// ---------------------------------------------------------------------------
// SGEMM: C[M,N] = A[M,K] @ B[K,N] (+bias[N]) (+resid[M,N]) (relu?)
// 128x128 tile, BK=8, 256 threads, 8x8 microtile, double-buffered smem.
// M,N multiples of 128; K multiple of 8.
// ---------------------------------------------------------------------------
__global__ __launch_bounds__(256, 2) void sgemm_kernel(
    const float* __restrict__ A, const float* __restrict__ B,
    const float* __restrict__ bias, const float* __restrict__ resid,
    float* __restrict__ C, int M, int N, int K, int relu)
{
    __shared__ float As[2][8][128];   // transposed: As[k][m]
    __shared__ float Bs[2][8][128];   // Bs[k][n]

    const int tid = threadIdx.x;
    const int tx = tid & 15, ty = tid >> 4;
    const int bx = blockIdx.x, by = blockIdx.y;

    const int arow = tid >> 1;             // 0..127
    const int acol = (tid & 1) * 4;        // 0 or 4
    const int brow = tid >> 5;             // 0..7
    const int bcol = (tid & 31) * 4;       // 0..124

    const float* Aptr = A + (size_t)(by * 128 + arow) * K + acol;
    const float* Bbase = B + (size_t)bx * 128 + bcol;

    float acc[8][8];
    #pragma unroll
    for (int i = 0; i < 8; i++)
        #pragma unroll
        for (int j = 0; j < 8; j++) acc[i][j] = 0.0f;

    // prime buffer 0
    float4 av = *reinterpret_cast<const float4*>(Aptr);
    float4 bv = *reinterpret_cast<const float4*>(Bbase + (size_t)brow * N);
    int cur = 0;
    As[0][acol + 0][arow] = av.x;
    As[0][acol + 1][arow] = av.y;
    As[0][acol + 2][arow] = av.z;
    As[0][acol + 3][arow] = av.w;
    *reinterpret_cast<float4*>(&Bs[0][brow][bcol]) = bv;
    __syncthreads();

    for (int k0 = 0; k0 < K; k0 += 8) {
        const bool nx = (k0 + 8) < K;
        if (nx) {
            av = *reinterpret_cast<const float4*>(Aptr + k0 + 8);
            bv = *reinterpret_cast<const float4*>(Bbase + (size_t)(k0 + 8 + brow) * N);
        }
        #pragma unroll
        for (int kk = 0; kk < 8; kk++) {
            float4 a0 = *reinterpret_cast<const float4*>(&As[cur][kk][ty * 4]);
            float4 a1 = *reinterpret_cast<const float4*>(&As[cur][kk][64 + ty * 4]);
            float4 b0 = *reinterpret_cast<const float4*>(&Bs[cur][kk][tx * 4]);
            float4 b1 = *reinterpret_cast<const float4*>(&Bs[cur][kk][64 + tx * 4]);
            float ar[8] = {a0.x, a0.y, a0.z, a0.w, a1.x, a1.y, a1.z, a1.w};
            float br[8] = {b0.x, b0.y, b0.z, b0.w, b1.x, b1.y, b1.z, b1.w};
            #pragma unroll
            for (int i = 0; i < 8; i++)
                #pragma unroll
                for (int j = 0; j < 8; j++)
                    acc[i][j] = fmaf(ar[i], br[j], acc[i][j]);
        }
        if (nx) {
            cur ^= 1;
            As[cur][acol + 0][arow] = av.x;
            As[cur][acol + 1][arow] = av.y;
            As[cur][acol + 2][arow] = av.z;
            As[cur][acol + 3][arow] = av.w;
            *reinterpret_cast<float4*>(&Bs[cur][brow][bcol]) = bv;
            __syncthreads();
        }
    }

    // epilogue
    #pragma unroll
    for (int ii = 0; ii < 2; ii++) {
        #pragma unroll
        for (int i4 = 0; i4 < 4; i4++) {
            const int r = by * 128 + ii * 64 + ty * 4 + i4;
            #pragma unroll
            for (int jj = 0; jj < 2; jj++) {
                const int c = bx * 128 + jj * 64 + tx * 4;
                float4 o;
                o.x = acc[ii * 4 + i4][jj * 4 + 0];
                o.y = acc[ii * 4 + i4][jj * 4 + 1];
                o.z = acc[ii * 4 + i4][jj * 4 + 2];
                o.w = acc[ii * 4 + i4][jj * 4 + 3];
                float4 bb = *reinterpret_cast<const float4*>(bias + c);
                o.x += bb.x; o.y += bb.y; o.z += bb.z; o.w += bb.w;
                if (resid) {
                    float4 rr = *reinterpret_cast<const float4*>(resid + (size_t)r * N + c);
                    o.x += rr.x; o.y += rr.y; o.z += rr.z; o.w += rr.w;
                }
                if (relu) {
                    o.x = fmaxf(o.x, 0.0f); o.y = fmaxf(o.y, 0.0f);
                    o.z = fmaxf(o.z, 0.0f); o.w = fmaxf(o.w, 0.0f);
                }
                *reinterpret_cast<float4*>(C + (size_t)r * N + c) = o;
            }
        }
    }
}

// ---------------------------------------------------------------------------
// Causal flash attention (fp32, online softmax).
// Block = (q-tile of 128 rows) x (head) x (batch), 256 threads.
// Key tiles of 128, only kt <= qt processed; diagonal tile masked.
// q,k,v layout: [B, S, H, DK] contiguous (== [B*S, D_MODEL] rows).
// ---------------------------------------------------------------------------
#define QST_PITCH 132           // [64 k][128 r]
#define KST_PITCH 132           // [64 k][128 j]
#define VS_PITCH  68            // [128 j][64 c]
#define ST_PITCH  132           // [128 j][128 r]   (S transposed)
#define SM_Q_OFF  0
#define SM_KV_OFF (64 * QST_PITCH)                   // 8448
#define SM_ST_OFF (SM_KV_OFF + 128 * VS_PITCH)       // 8448 + 8704 = 17152
#define SM_M_OFF  (SM_ST_OFF + 128 * ST_PITCH)       // +16896 = 34048
#define SM_L_OFF  (SM_M_OFF + 128)
#define SM_SC_OFF (SM_L_OFF + 128)
#define ATTN_SMEM_FLOATS (SM_SC_OFF + 128)           // 34432
#define ATTN_SMEM_BYTES  (ATTN_SMEM_FLOATS * 4)      // 137728

__global__ __launch_bounds__(256) void attn_kernel(
    const float* __restrict__ Q, const float* __restrict__ Kg,
    const float* __restrict__ Vg, float* __restrict__ O)
{
    extern __shared__ float sm[];
    float* Qst = sm + SM_Q_OFF;
    float* KV  = sm + SM_KV_OFF;
    float* St  = sm + SM_ST_OFF;
    float* m_s = sm + SM_M_OFF;
    float* l_s = sm + SM_L_OFF;
    float* sc_s = sm + SM_SC_OFF;

    const int qt = blockIdx.x, hh = blockIdx.y, bb = blockIdx.z;
    const int tid = threadIdx.x;
    const int tx = tid & 15, ty = tid >> 4;
    const int qbase = qt * 128;
    const size_t base = ((size_t)bb * S_LEN) * D_MODEL + (size_t)hh * DK;

    // load Q tile transposed: Qst[k][r]
    #pragma unroll
    for (int i = 0; i < 8; i++) {
        int f = tid + i * 256;            // 0..2047
        int r = f >> 4;
        int k4 = (f & 15) * 4;
        float4 qv = *reinterpret_cast<const float4*>(
            Q + base + (size_t)(qbase + r) * D_MODEL + k4);
        Qst[(k4 + 0) * QST_PITCH + r] = qv.x;
        Qst[(k4 + 1) * QST_PITCH + r] = qv.y;
        Qst[(k4 + 2) * QST_PITCH + r] = qv.z;
        Qst[(k4 + 3) * QST_PITCH + r] = qv.w;
    }
    if (tid < 128) { m_s[tid] = -INFINITY; l_s[tid] = 0.0f; }

    float o[8][4];
    #pragma unroll
    for (int i = 0; i < 8; i++)
        #pragma unroll
        for (int c = 0; c < 4; c++) o[i][c] = 0.0f;

    for (int kt = 0; kt <= qt; kt++) {
        const int kbase = kt * 128;
        // load K tile transposed: KV[k][j] (pitch 132)
        #pragma unroll
        for (int i = 0; i < 8; i++) {
            int f = tid + i * 256;
            int j = f >> 4;
            int k4 = (f & 15) * 4;
            float4 kv = *reinterpret_cast<const float4*>(
                Kg + base + (size_t)(kbase + j) * D_MODEL + k4);
            KV[(k4 + 0) * KST_PITCH + j] = kv.x;
            KV[(k4 + 1) * KST_PITCH + j] = kv.y;
            KV[(k4 + 2) * KST_PITCH + j] = kv.z;
            KV[(k4 + 3) * KST_PITCH + j] = kv.w;
        }
        __syncthreads();   // (A) Q + K ready, KV free of old V

        // scores: thread owns rows ty*8..+7, cols tx + jj*16
        float s[8][8];
        #pragma unroll
        for (int i = 0; i < 8; i++)
            #pragma unroll
            for (int j = 0; j < 8; j++) s[i][j] = 0.0f;

        #pragma unroll 8
        for (int k = 0; k < DK; k++) {
            float4 q0 = *reinterpret_cast<const float4*>(&Qst[k * QST_PITCH + ty * 8]);
            float4 q1 = *reinterpret_cast<const float4*>(&Qst[k * QST_PITCH + ty * 8 + 4]);
            float qr[8] = {q0.x, q0.y, q0.z, q0.w, q1.x, q1.y, q1.z, q1.w};
            float kc[8];
            #pragma unroll
            for (int jj = 0; jj < 8; jj++)
                kc[jj] = KV[k * KST_PITCH + tx + jj * 16];
            #pragma unroll
            for (int i = 0; i < 8; i++)
                #pragma unroll
                for (int jj = 0; jj < 8; jj++)
                    s[i][jj] = fmaf(qr[i], kc[jj], s[i][jj]);
        }
        // mask + scale + store transposed St[j][r]
        #pragma unroll
        for (int i = 0; i < 8; i++) {
            const int qi = qbase + ty * 8 + i;
            #pragma unroll
            for (int jj = 0; jj < 8; jj++) {
                const int kj = kbase + tx + jj * 16;
                float v = (kj <= qi) ? s[i][jj] * 0.125f : -1e30f;
                St[(tx + jj * 16) * ST_PITCH + ty * 8 + i] = v;
            }
        }
        __syncthreads();   // (B) St complete, K consumed -> KV reusable

        // load V tile: KV[j][c] pitch 68  (overlaps with softmax below)
        #pragma unroll
        for (int i = 0; i < 8; i++) {
            int f = tid + i * 256;
            int j = f >> 4;
            int c4 = (f & 15) * 4;
            float4 vv = *reinterpret_cast<const float4*>(
                Vg + base + (size_t)(kbase + j) * D_MODEL + c4);
            *reinterpret_cast<float4*>(&KV[j * VS_PITCH + c4]) = vv;
        }
        // online softmax: thread t < 128 owns row t
        if (tid < 128) {
            const int r = tid;
            float mx = m_s[r];
            float tmax = -INFINITY;
            #pragma unroll 4
            for (int j = 0; j < 128; j++)
                tmax = fmaxf(tmax, St[j * ST_PITCH + r]);
            const float nm = fmaxf(mx, tmax);
            float sum = 0.0f;
            #pragma unroll 4
            for (int j = 0; j < 128; j++) {
                float p = __expf(St[j * ST_PITCH + r] - nm);
                St[j * ST_PITCH + r] = p;
                sum += p;
            }
            const float sc = __expf(mx - nm);   // 0 when mx = -inf
            l_s[r] = l_s[r] * sc + sum;
            m_s[r] = nm;
            sc_s[r] = sc;
        }
        __syncthreads();   // (C) P + V + scales ready

        // rescale accumulators
        #pragma unroll
        for (int i = 0; i < 8; i++) {
            const float sc = sc_s[ty * 8 + i];
            #pragma unroll
            for (int c = 0; c < 4; c++) o[i][c] *= sc;
        }
        // O += P @ V : thread owns rows ty*8..+7, cols tx*4..+3
        #pragma unroll 4
        for (int j = 0; j < 128; j++) {
            float4 p0 = *reinterpret_cast<const float4*>(&St[j * ST_PITCH + ty * 8]);
            float4 p1 = *reinterpret_cast<const float4*>(&St[j * ST_PITCH + ty * 8 + 4]);
            float pr[8] = {p0.x, p0.y, p0.z, p0.w, p1.x, p1.y, p1.z, p1.w};
            float4 vv = *reinterpret_cast<const float4*>(&KV[j * VS_PITCH + tx * 4]);
            float vc[4] = {vv.x, vv.y, vv.z, vv.w};
            #pragma unroll
            for (int i = 0; i < 8; i++)
                #pragma unroll
                for (int c = 0; c < 4; c++)
                    o[i][c] = fmaf(pr[i], vc[c], o[i][c]);
        }
        __syncthreads();   // (D) KV/St free for next iteration
    }

    // write out: O[b, qbase+r, h, tx*4..]
    #pragma unroll
    for (int i = 0; i < 8; i++) {
        const int r = ty * 8 + i;
        const float inv = 1.0f / l_s[r];
        float4 ov;
        ov.x = o[i][0] * inv; ov.y = o[i][1] * inv;
        ov.z = o[i][2] * inv; ov.w = o[i][3] * inv;
        *reinterpret_cast<float4*>(
            O + base + (size_t)(qbase + r) * D_MODEL + tx * 4) = ov;
    }
}

// ---------------------------------------------------------------------------
// kernel_launch
// Inputs (metadata order): x, mask, Wq, bq, Wk, bk, Wv, bv, Wo, bo,
//                          W1, b1, W2, b2, ln1_g, ln1_b, ln2_g, ln2_b
// ---------------------------------------------------------------------------
extern "C" void kernel_launch(void* const* d_in, const int* in_sizes, int n_in,
                              void* d_out, int out_size)
{
    const float* x   = (const float*)d_in[0];
    // d_in[1] = mask (causal, known statically — unused)
    const float* Wq  = (const float*)d_in[2];
    const float* bq  = (const float*)d_in[3];
    const float* Wk  = (const float*)d_in[4];
    const float* bk  = (const float*)d_in[5];
    const float* Wv  = (const float*)d_in[6];
    const float* bv  = (const float*)d_in[7];
    const float* Wo  = (const float*)d_in[8];
    const float* bo  = (const float*)d_in[9];
    const float* W1  = (const float*)d_in[10];
    const float* b1  = (const float*)d_in[11];
    const float* W2  = (const float*)d_in[12];
    const float* b2  = (const float*)d_in[13];
    const float* g1  = (const float*)d_in[14];
    const float* be1 = (const float*)d_in[15];
    const float* g2  = (const float*)d_in[16];
    const float* be2 = (const float*)d_in[17];
    float* out = (float*)d_out;

    float *xn, *q, *k, *v, *at, *h, *hn, *ff;
    cudaGetSymbolAddress((void**)&xn, g_xn);
    cudaGetSymbolAddress((void**)&q,  g_q);
    cudaGetSymbolAddress((void**)&k,  g_k);
    cudaGetSymbolAddress((void**)&v,  g_v);
    cudaGetSymbolAddress((void**)&at, g_at);
    cudaGetSymbolAddress((void**)&h,  g_h);
    cudaGetSymbolAddress((void**)&hn, g_hn);
    cudaGetSymbolAddress((void**)&ff, g_ff);

    cudaFuncSetAttribute(attn_kernel,
                         cudaFuncAttributeMaxDynamicSharedMemorySize,
                         ATTN_SMEM_BYTES);

    const dim3 blk(256);
    const dim3 gN1024(D_MODEL / 128, MROWS / 128);  // (8, 32)
    const dim3 gN4096(DFF / 128, MROWS / 128);      // (32, 32)

    // xn = LN1(x)
    ln_kernel<<<MROWS, blk>>>(x, g1, be1, xn);
    // q/k/v = xn @ W{q,k,v} + b
    sgemm_kernel<<<gN1024, blk>>>(xn, Wq, bq, nullptr, q, MROWS, D_MODEL, D_MODEL, 0);
    sgemm_kernel<<<gN1024, blk>>>(xn, Wk, bk, nullptr, k, MROWS, D_MODEL, D_MODEL, 0);
    sgemm_kernel<<<gN1024, blk>>>(xn, Wv, bv, nullptr, v, MROWS, D_MODEL, D_MODEL, 0);
    // causal attention
    attn_kernel<<<dim3(S_LEN / 128, NH, BATCH), blk, ATTN_SMEM_BYTES>>>(q, k, v, at);
    // h = x + attn @ Wo + bo
    sgemm_kernel<<<gN1024, blk>>>(at, Wo, bo, x, h, MROWS, D_MODEL, D_MODEL, 0);
    // hn = LN2(h)
    ln_kernel<<<MROWS, blk>>>(h, g2, be2, hn);
    // ff = relu(hn @ W1 + b1)
    sgemm_kernel<<<gN4096, blk>>>(hn, W1, b1, nullptr, ff, MROWS, DFF, D_MODEL, 1);
    // out = h + ff @ W2 + b2
    sgemm_kernel<<<gN1024, blk>>>(ff, W2, b2, h, out, MROWS, D_MODEL, DFF, 0);
}

// round 3
// speedup vs baseline: 1.6397x; 1.6397x over previous
#include <cuda_runtime.h>
#include <cuda_bf16.h>
#include <math.h>
#include <stdint.h>

// Problem constants
#define D_MODEL 1024
#define S_LEN   2048
#define BATCH   2
#define NH      16
#define DK      64
#define DFF     4096
#define MROWS   (BATCH * S_LEN)   // 4096
#define QKV_N   3072
#define QKV_PITCH 3072

typedef __nv_bfloat16 bf16;

// ---------------------------------------------------------------------------
// Scratch (device globals — no allocation allowed)
// ---------------------------------------------------------------------------
__device__ bf16  g_xn_h[(size_t)MROWS * D_MODEL];
__device__ bf16  g_xn_l[(size_t)MROWS * D_MODEL];
__device__ float g_qkv [(size_t)MROWS * QKV_N];
__device__ bf16  g_at_h[(size_t)MROWS * D_MODEL];
__device__ bf16  g_at_l[(size_t)MROWS * D_MODEL];
__device__ float g_h   [(size_t)MROWS * D_MODEL];
__device__ bf16  g_hn_h[(size_t)MROWS * D_MODEL];
__device__ bf16  g_hn_l[(size_t)MROWS * D_MODEL];
__device__ bf16  g_ff_h[(size_t)MROWS * DFF];
__device__ bf16  g_ff_l[(size_t)MROWS * DFF];
// transposed split weights: WT[n][k]
__device__ bf16  g_wqkvT_h[(size_t)QKV_N * D_MODEL];
__device__ bf16  g_wqkvT_l[(size_t)QKV_N * D_MODEL];
__device__ bf16  g_woT_h[(size_t)D_MODEL * D_MODEL];
__device__ bf16  g_woT_l[(size_t)D_MODEL * D_MODEL];
__device__ bf16  g_w1T_h[(size_t)DFF * D_MODEL];
__device__ bf16  g_w1T_l[(size_t)DFF * D_MODEL];
__device__ bf16  g_w2T_h[(size_t)D_MODEL * DFF];
__device__ bf16  g_w2T_l[(size_t)D_MODEL * DFF];
__device__ float g_bqkv[QKV_N];

__device__ __forceinline__ void split_bf16(float v, bf16& h, bf16& l) {
    h = __float2bfloat16(v);
    l = __float2bfloat16(v - __bfloat162float(h));
}

// ---------------------------------------------------------------------------
// Weight transpose + split: W[K][N] fp32 -> WT_h/WT_l [N][K] bf16
// ---------------------------------------------------------------------------
__global__ __launch_bounds__(256) void wconv_kernel(
    const float* __restrict__ W, bf16* __restrict__ Th, bf16* __restrict__ Tl,
    int K, int N)
{
    __shared__ float t[32][33];
    const int tx = threadIdx.x, ty = threadIdx.y;
    const int n0 = blockIdx.x * 32, k0 = blockIdx.y * 32;
    #pragma unroll
    for (int i = 0; i < 4; i++)
        t[ty + i * 8][tx] = W[(size_t)(k0 + ty + i * 8) * N + n0 + tx];
    __syncthreads();
    #pragma unroll
    for (int i = 0; i < 4; i++) {
        float v = t[tx][ty + i * 8];
        bf16 h, l; split_bf16(v, h, l);
        size_t o = (size_t)(n0 + ty + i * 8) * K + k0 + tx;
        Th[o] = h; Tl[o] = l;
    }
}

__global__ void bias_concat_kernel(const float* bq, const float* bk, const float* bv,
                                   float* out) {
    int i = blockIdx.x * 1024 + threadIdx.x;
    out[i] = (i < 1024) ? bq[i] : (i < 2048) ? bk[i - 1024] : bv[i - 2048];
}

// ---------------------------------------------------------------------------
// LayerNorm -> bf16 hi/lo split output
// ---------------------------------------------------------------------------
__device__ __forceinline__ float block_sum_256(float v, float* red) {
    __syncthreads();
    #pragma unroll
    for (int o = 16; o; o >>= 1) v += __shfl_xor_sync(0xffffffffu, v, o);
    if ((threadIdx.x & 31) == 0) red[threadIdx.x >> 5] = v;
    __syncthreads();
    if (threadIdx.x < 32) {
        float w = (threadIdx.x < 8) ? red[threadIdx.x] : 0.0f;
        #pragma unroll
        for (int o = 4; o; o >>= 1) w += __shfl_xor_sync(0xffffffffu, w, o);
        if (threadIdx.x == 0) red[0] = w;
    }
    __syncthreads();
    return red[0];
}

__global__ __launch_bounds__(256) void ln_split_kernel(
    const float* __restrict__ x, const float* __restrict__ g,
    const float* __restrict__ b, bf16* __restrict__ oh, bf16* __restrict__ ol)
{
    __shared__ float red[32];
    const int row = blockIdx.x;
    const int t = threadIdx.x;
    float4 v = reinterpret_cast<const float4*>(x + (size_t)row * D_MODEL)[t];

    float s = v.x + v.y + v.z + v.w;
    float mu = block_sum_256(s, red) * (1.0f / (float)D_MODEL);

    float dx = v.x - mu, dy = v.y - mu, dz = v.z - mu, dw = v.w - mu;
    float sq = dx * dx + dy * dy + dz * dz + dw * dw;
    float var = block_sum_256(sq, red) * (1.0f / (float)D_MODEL);
    float inv = rsqrtf(var + 1e-5f);

    float4 gg = reinterpret_cast<const float4*>(g)[t];
    float4 bb = reinterpret_cast<const float4*>(b)[t];
    float o0 = dx * inv * gg.x + bb.x;
    float o1 = dy * inv * gg.y + bb.y;
    float o2 = dz * inv * gg.z + bb.z;
    float o3 = dw * inv * gg.w + bb.w;

    bf16 h0, l0, h1, l1, h2, l2, h3, l3;
    split_bf16(o0, h0, l0); split_bf16(o1, h1, l1);
    split_bf16(o2, h2, l2); split_bf16(o3, h3, l3);
    size_t off = (size_t)row * D_MODEL + t * 4;
    __nv_bfloat162* ph = reinterpret_cast<__nv_bfloat162*>(oh + off);
    ph[0] = __halves2bfloat162(h0, h1);
    ph[1] = __halves2bfloat162(h2, h3);
    __nv_bfloat162* pl = reinterpret_cast<__nv_bfloat162*>(ol + off);
    pl[0] = __halves2bfloat162(l0, l1);
    pl[1] = __halves2bfloat162(l2, l3);
}

// ---------------------------------------------------------------------------
// bf16 split-precision tensor-core GEMM.
// C[M,N] = A[M,K]@B^T[N,K] (+bias) (+resid) (relu?), fp32 accumulate via
// 3 mma passes: Ah*Bh + Ah*Bl + Al*Bh.
// Tiles: 128x128x32, 256 threads (8 warps, 2x4 warp grid, 64x32 warp tiles).
// cp.async 3-stage pipeline. A,B given as bf16 hi/lo, both row-major over K.
// ---------------------------------------------------------------------------
#define BK 32
#define APITCH 40                 // bf16 pitch (32 + 8 pad) -> conflict-free
#define PART_BF (128 * APITCH)    // 5120 bf16 per matrix per stage
#define STAGE_BF (4 * PART_BF)    // Ah, Al, Bh, Bl
#define STAGES 3
#define GEMM_SMEM_BYTES (STAGES * STAGE_BF * 2)   // 122880

__device__ __forceinline__ uint32_t lds32(const bf16* p) {
    return *reinterpret_cast<const uint32_t*>(p);
}

__device__ __forceinline__ void mma_bf16(float c[4], const uint32_t a[4],
                                         const uint32_t b[2]) {
    asm volatile(
        "mma.sync.aligned.m16n8k16.row.col.f32.bf16.bf16.f32 "
        "{%0,%1,%2,%3}, {%4,%5,%6,%7}, {%8,%9}, {%0,%1,%2,%3};"
        : "+f"(c[0]), "+f"(c[1]), "+f"(c[2]), "+f"(c[3])
        : "r"(a[0]), "r"(a[1]), "r"(a[2]), "r"(a[3]), "r"(b[0]), "r"(b[1]));
}

__global__ __launch_bounds__(256) void gemm_bf16_kernel(
    const bf16* __restrict__ Ah, const bf16* __restrict__ Al,
    const bf16* __restrict__ Bh, const bf16* __restrict__ Bl,
    const float* __restrict__ bias, const float* __restrict__ resid,
    float* __restrict__ Cf, bf16* __restrict__ Ch, bf16* __restrict__ Cl,
    int M, int N, int K, int relu)
{
    extern __shared__ bf16 smb[];
    const int tid = threadIdx.x;
    const int lane = tid & 31;
    const int w = tid >> 5;
    const int wm = w & 1, wn = w >> 1;         // 2 x 4 warp grid
    const int g = lane >> 2, tg = lane & 3;
    const int bx = blockIdx.x, by = blockIdx.y;

    const bf16* Asrc[2] = {Ah + (size_t)(by * 128) * K, Al + (size_t)(by * 128) * K};
    const bf16* Bsrc[2] = {Bh + (size_t)(bx * 128) * K, Bl + (size_t)(bx * 128) * K};

    uint32_t smem_base = (uint32_t)__cvta_generic_to_shared(smb);

    float acc[4][4][4];
    #pragma unroll
    for (int mi = 0; mi < 4; mi++)
        #pragma unroll
        for (int ni = 0; ni < 4; ni++)
            #pragma unroll
            for (int c = 0; c < 4; c++) acc[mi][ni][c] = 0.0f;

    const int nk = K / BK;

    // per-thread load mapping: 2 x 16B chunks per matrix per stage
    const int row0 = tid >> 2, seg0 = tid & 3;         // chunk tid
    const int row1 = (tid + 256) >> 2, seg1 = tid & 3; // chunk tid+256

#define LOAD_STAGE(s, k0)                                                     \
    do {                                                                      \
        uint32_t sb = smem_base + (s) * (STAGE_BF * 2);                       \
        _Pragma("unroll")                                                     \
        for (int p = 0; p < 2; p++) {                                         \
            uint32_t d0 = sb + p * (PART_BF * 2) + row0 * 80 + seg0 * 16;     \
            uint32_t d1 = sb + p * (PART_BF * 2) + row1 * 80 + seg1 * 16;     \
            const bf16* s0 = Asrc[p] + (size_t)row0 * K + (k0) + seg0 * 8;    \
            const bf16* s1 = Asrc[p] + (size_t)row1 * K + (k0) + seg1 * 8;    \
            asm volatile("cp.async.cg.shared.global [%0], [%1], 16;" ::       \
                         "r"(d0), "l"(s0));                                   \
            asm volatile("cp.async.cg.shared.global [%0], [%1], 16;" ::       \
                         "r"(d1), "l"(s1));                                   \
        }                                                                     \
        _Pragma("unroll")                                                     \
        for (int p = 0; p < 2; p++) {                                         \
            uint32_t d0 = sb + (p + 2) * (PART_BF * 2) + row0 * 80 + seg0 * 16;\
            uint32_t d1 = sb + (p + 2) * (PART_BF * 2) + row1 * 80 + seg1 * 16;\
            const bf16* s0 = Bsrc[p] + (size_t)row0 * K + (k0) + seg0 * 8;    \
            const bf16* s1 = Bsrc[p] + (size_t)row1 * K + (k0) + seg1 * 8;    \
            asm volatile("cp.async.cg.shared.global [%0], [%1], 16;" ::       \
                         "r"(d0), "l"(s0));                                   \
            asm volatile("cp.async.cg.shared.global [%0], [%1], 16;" ::       \
                         "r"(d1), "l"(s1));                                   \
        }                                                                     \
        asm volatile("cp.async.commit_group;");                               \
    } while (0)

    LOAD_STAGE(0, 0);
    LOAD_STAGE(1, BK);

    for (int kt = 0; kt < nk; kt++) {
        asm volatile("cp.async.wait_group %0;" :: "n"(STAGES - 2));
        __syncthreads();

        const int buf = kt % STAGES;
        const bf16* sAh = smb + buf * STAGE_BF;
        const bf16* sAl = sAh + PART_BF;
        const bf16* sBh = sAh + 2 * PART_BF;
        const bf16* sBl = sAh + 3 * PART_BF;

        #pragma unroll
        for (int kf = 0; kf < 2; kf++) {
            uint32_t fAh[4][4], fAl[4][4], fBh[4][2], fBl[4][2];
            const int cA = kf * 16 + tg * 2;
            #pragma unroll
            for (int mi = 0; mi < 4; mi++) {
                const int r = wm * 64 + mi * 16 + g;
                fAh[mi][0] = lds32(sAh + r * APITCH + cA);
                fAh[mi][1] = lds32(sAh + (r + 8) * APITCH + cA);
                fAh[mi][2] = lds32(sAh + r * APITCH + cA + 8);
                fAh[mi][3] = lds32(sAh + (r + 8) * APITCH + cA + 8);
                fAl[mi][0] = lds32(sAl + r * APITCH + cA);
                fAl[mi][1] = lds32(sAl + (r + 8) * APITCH + cA);
                fAl[mi][2] = lds32(sAl + r * APITCH + cA + 8);
                fAl[mi][3] = lds32(sAl + (r + 8) * APITCH + cA + 8);
            }
            #pragma unroll
            for (int ni = 0; ni < 4; ni++) {
                const int r = wn * 32 + ni * 8 + g;
                fBh[ni][0] = lds32(sBh + r * APITCH + cA);
                fBh[ni][1] = lds32(sBh + r * APITCH + cA + 8);
                fBl[ni][0] = lds32(sBl + r * APITCH + cA);
                fBl[ni][1] = lds32(sBl + r * APITCH + cA + 8);
            }
            #pragma unroll
            for (int mi = 0; mi < 4; mi++)
                #pragma unroll
                for (int ni = 0; ni < 4; ni++) {
                    mma_bf16(acc[mi][ni], fAh[mi], fBh[ni]);
                    mma_bf16(acc[mi][ni], fAh[mi], fBl[ni]);
                    mma_bf16(acc[mi][ni], fAl[mi], fBh[ni]);
                }
        }

        const int knext = kt + STAGES - 1;
        if (knext < nk) {
            LOAD_STAGE(knext % STAGES, knext * BK);
        } else {
            asm volatile("cp.async.commit_group;");
        }
    }

    // epilogue
    const int bm = by * 128 + wm * 64;
    const int bn = bx * 128 + wn * 32;
    #pragma unroll
    for (int mi = 0; mi < 4; mi++) {
        #pragma unroll
        for (int ni = 0; ni < 4; ni++) {
            const int c0 = bn + ni * 8 + tg * 2;
            const float b0 = bias[c0], b1 = bias[c0 + 1];
            #pragma unroll
            for (int half = 0; half < 2; half++) {
                const int r = bm + mi * 16 + g + half * 8;
                float v0 = acc[mi][ni][half * 2 + 0] + b0;
                float v1 = acc[mi][ni][half * 2 + 1] + b1;
                if (resid) {
                    const float2 rr = *reinterpret_cast<const float2*>(
                        resid + (size_t)r * N + c0);
                    v0 += rr.x; v1 += rr.y;
                }
                if (relu) { v0 = fmaxf(v0, 0.0f); v1 = fmaxf(v1, 0.0f); }
                if (Cf) {
                    float2 o; o.x = v0; o.y = v1;
                    *reinterpret_cast<float2*>(Cf + (size_t)r * N + c0) = o;
                }
                if (Ch) {
                    bf16 h0, l0, h1, l1;
                    split_bf16(v0, h0, l0); split_bf16(v1, h1, l1);
                    *reinterpret_cast<__nv_bfloat162*>(Ch + (size_t)r * N + c0) =
                        __halves2bfloat162(h0, h1);
                    *reinterpret_cast<__nv_bfloat162*>(Cl + (size_t)r * N + c0) =
                        __halves2bfloat162(l0, l1);
                }
            }
        }
    }
}

// ---------------------------------------------------------------------------
// Causal flash attention (fp32, online softmax). Reads fused qkv buffer
// (row pitch QKV_PITCH). Writes bf16 hi/lo split output.
// ---------------------------------------------------------------------------
#define QST_PITCH 132
#define KST_PITCH 132
#define VS_PITCH  68
#define ST_PITCH  132
#define SM_Q_OFF  0
#define SM_KV_OFF (64 * QST_PITCH)
#define SM_ST_OFF (SM_KV_OFF + 128 * VS_PITCH)
#define SM_M_OFF  (SM_ST_OFF + 128 * ST_PITCH)
#define SM_L_OFF  (SM_M_OFF + 128)
#define SM_SC_OFF (SM_L_OFF + 128)
#define ATTN_SMEM_FLOATS (SM_SC_OFF + 128)
#define ATTN_SMEM_BYTES  (ATTN_SMEM_FLOATS * 4)

__global__ __launch_bounds__(256) void attn_kernel(
    const float* __restrict__ Q, const float* __restrict__ Kg,
    const float* __restrict__ Vg, bf16* __restrict__ Oh, bf16* __restrict__ Ol)
{
    extern __shared__ float sm[];
    float* Qst = sm + SM_Q_OFF;
    float* KV  = sm + SM_KV_OFF;
    float* St  = sm + SM_ST_OFF;
    float* m_s = sm + SM_M_OFF;
    float* l_s = sm + SM_L_OFF;
    float* sc_s = sm + SM_SC_OFF;

    const int qt = blockIdx.x, hh = blockIdx.y, bb = blockIdx.z;
    const int tid = threadIdx.x;
    const int tx = tid & 15, ty = tid >> 4;
    const int qbase = qt * 128;
    const size_t base = ((size_t)bb * S_LEN) * QKV_PITCH + (size_t)hh * DK;

    #pragma unroll
    for (int i = 0; i < 8; i++) {
        int f = tid + i * 256;
        int r = f >> 4;
        int k4 = (f & 15) * 4;
        float4 qv = *reinterpret_cast<const float4*>(
            Q + base + (size_t)(qbase + r) * QKV_PITCH + k4);
        Qst[(k4 + 0) * QST_PITCH + r] = qv.x;
        Qst[(k4 + 1) * QST_PITCH + r] = qv.y;
        Qst[(k4 + 2) * QST_PITCH + r] = qv.z;
        Qst[(k4 + 3) * QST_PITCH + r] = qv.w;
    }
    if (tid < 128) { m_s[tid] = -INFINITY; l_s[tid] = 0.0f; }

    float o[8][4];
    #pragma unroll
    for (int i = 0; i < 8; i++)
        #pragma unroll
        for (int c = 0; c < 4; c++) o[i][c] = 0.0f;

    for (int kt = 0; kt <= qt; kt++) {
        const int kbase = kt * 128;
        #pragma unroll
        for (int i = 0; i < 8; i++) {
            int f = tid + i * 256;
            int j = f >> 4;
            int k4 = (f & 15) * 4;
            float4 kv = *reinterpret_cast<const float4*>(
                Kg + base + (size_t)(kbase + j) * QKV_PITCH + k4);
            KV[(k4 + 0) * KST_PITCH + j] = kv.x;
            KV[(k4 + 1) * KST_PITCH + j] = kv.y;
            KV[(k4 + 2) * KST_PITCH + j] = kv.z;
            KV[(k4 + 3) * KST_PITCH + j] = kv.w;
        }
        __syncthreads();

        float s[8][8];
        #pragma unroll
        for (int i = 0; i < 8; i++)
            #pragma unroll
            for (int j = 0; j < 8; j++) s[i][j] = 0.0f;

        #pragma unroll 8
        for (int k = 0; k < DK; k++) {
            float4 q0 = *reinterpret_cast<const float4*>(&Qst[k * QST_PITCH + ty * 8]);
            float4 q1 = *reinterpret_cast<const float4*>(&Qst[k * QST_PITCH + ty * 8 + 4]);
            float qr[8] = {q0.x, q0.y, q0.z, q0.w, q1.x, q1.y, q1.z, q1.w};
            float kc[8];
            #pragma unroll
            for (int jj = 0; jj < 8; jj++)
                kc[jj] = KV[k * KST_PITCH + tx + jj * 16];
            #pragma unroll
            for (int i = 0; i < 8; i++)
                #pragma unroll
                for (int jj = 0; jj < 8; jj++)
                    s[i][jj] = fmaf(qr[i], kc[jj], s[i][jj]);
        }
        #pragma unroll
        for (int i = 0; i < 8; i++) {
            const int qi = qbase + ty * 8 + i;
            #pragma unroll
            for (int jj = 0; jj < 8; jj++) {
                const int kj = kbase + tx + jj * 16;
                float v = (kj <= qi) ? s[i][jj] * 0.125f : -1e30f;
                St[(tx + jj * 16) * ST_PITCH + ty * 8 + i] = v;
            }
        }
        __syncthreads();

        #pragma unroll
        for (int i = 0; i < 8; i++) {
            int f = tid + i * 256;
            int j = f >> 4;
            int c4 = (f & 15) * 4;
            float4 vv = *reinterpret_cast<const float4*>(
                Vg + base + (size_t)(kbase + j) * QKV_PITCH + c4);
            *reinterpret_cast<float4*>(&KV[j * VS_PITCH + c4]) = vv;
        }
        if (tid < 128) {
            const int r = tid;
            float mx = m_s[r];
            float tmax = -INFINITY;
            #pragma unroll 4
            for (int j = 0; j < 128; j++)
                tmax = fmaxf(tmax, St[j * ST_PITCH + r]);
            const float nm = fmaxf(mx, tmax);
            float sum = 0.0f;
            #pragma unroll 4
            for (int j = 0; j < 128; j++) {
                float p = __expf(St[j * ST_PITCH + r] - nm);
                St[j * ST_PITCH + r] = p;
                sum += p;
            }
            const float sc = __expf(mx - nm);
            l_s[r] = l_s[r] * sc + sum;
            m_s[r] = nm;
            sc_s[r] = sc;
        }
        __syncthreads();

        #pragma unroll
        for (int i = 0; i < 8; i++) {
            const float sc = sc_s[ty * 8 + i];
            #pragma unroll
            for (int c = 0; c < 4; c++) o[i][c] *= sc;
        }
        #pragma unroll 4
        for (int j = 0; j < 128; j++) {
            float4 p0 = *reinterpret_cast<const float4*>(&St[j * ST_PITCH + ty * 8]);
            float4 p1 = *reinterpret_cast<const float4*>(&St[j * ST_PITCH + ty * 8 + 4]);
            float pr[8] = {p0.x, p0.y, p0.z, p0.w, p1.x, p1.y, p1.z, p1.w};
            float4 vv = *reinterpret_cast<const float4*>(&KV[j * VS_PITCH + tx * 4]);
            float vc[4] = {vv.x, vv.y, vv.z, vv.w};
            #pragma unroll
            for (int i = 0; i < 8; i++)
                #pragma unroll
                for (int c = 0; c < 4; c++)
                    o[i][c] = fmaf(pr[i], vc[c], o[i][c]);
        }
        __syncthreads();
    }

    // write bf16 hi/lo split output at [B*S, D_MODEL] pitch
    #pragma unroll
    for (int i = 0; i < 8; i++) {
        const int r = ty * 8 + i;
        const float inv = 1.0f / l_s[r];
        float v0 = o[i][0] * inv, v1 = o[i][1] * inv;
        float v2 = o[i][2] * inv, v3 = o[i][3] * inv;
        bf16 h0, l0, h1, l1, h2, l2, h3, l3;
        split_bf16(v0, h0, l0); split_bf16(v1, h1, l1);
        split_bf16(v2, h2, l2); split_bf16(v3, h3, l3);
        size_t off = ((size_t)bb * S_LEN + qbase + r) * D_MODEL + hh * DK + tx * 4;
        __nv_bfloat162* ph = reinterpret_cast<__nv_bfloat162*>(Oh + off);
        ph[0] = __halves2bfloat162(h0, h1);
        ph[1] = __halves2bfloat162(h2, h3);
        __nv_bfloat162* pl = reinterpret_cast<__nv_bfloat162*>(Ol + off);
        pl[0] = __halves2bfloat162(l0, l1);
        pl[1] = __halves2bfloat162(l2, l3);
    }
}

// ---------------------------------------------------------------------------
// kernel_launch
// ---------------------------------------------------------------------------
extern "C" void kernel_launch(void* const* d_in, const int* in_sizes, int n_in,
                              void* d_out, int out_size)
{
    const float* x   = (const float*)d_in[0];
    const float* Wq  = (const float*)d_in[2];
    const float* bq  = (const float*)d_in[3];
    const float* Wk  = (const float*)d_in[4];
    const float* bk  = (const float*)d_in[5];
    const float* Wv  = (const float*)d_in[6];
    const float* bv  = (const float*)d_in[7];
    const float* Wo  = (const float*)d_in[8];
    const float* bo  = (const float*)d_in[9];
    const float* W1  = (const float*)d_in[10];
    const float* b1  = (const float*)d_in[11];
    const float* W2  = (const float*)d_in[12];
    const float* b2  = (const float*)d_in[13];
    const float* g1  = (const float*)d_in[14];
    const float* be1 = (const float*)d_in[15];
    const float* g2  = (const float*)d_in[16];
    const float* be2 = (const float*)d_in[17];
    float* out = (float*)d_out;

    bf16 *xnh, *xnl, *ath, *atl, *hnh, *hnl, *ffh, *ffl;
    bf16 *wqkvh, *wqkvl, *woh, *wol, *w1h, *w1l, *w2h, *w2l;
    float *qkv, *h, *bqkv;
    cudaGetSymbolAddress((void**)&xnh, g_xn_h);
    cudaGetSymbolAddress((void**)&xnl, g_xn_l);
    cudaGetSymbolAddress((void**)&qkv, g_qkv);
    cudaGetSymbolAddress((void**)&ath, g_at_h);
    cudaGetSymbolAddress((void**)&atl, g_at_l);
    cudaGetSymbolAddress((void**)&h,   g_h);
    cudaGetSymbolAddress((void**)&hnh, g_hn_h);
    cudaGetSymbolAddress((void**)&hnl, g_hn_l);
    cudaGetSymbolAddress((void**)&ffh, g_ff_h);
    cudaGetSymbolAddress((void**)&ffl, g_ff_l);
    cudaGetSymbolAddress((void**)&wqkvh, g_wqkvT_h);
    cudaGetSymbolAddress((void**)&wqkvl, g_wqkvT_l);
    cudaGetSymbolAddress((void**)&woh, g_woT_h);
    cudaGetSymbolAddress((void**)&wol, g_woT_l);
    cudaGetSymbolAddress((void**)&w1h, g_w1T_h);
    cudaGetSymbolAddress((void**)&w1l, g_w1T_l);
    cudaGetSymbolAddress((void**)&w2h, g_w2T_h);
    cudaGetSymbolAddress((void**)&w2l, g_w2T_l);
    cudaGetSymbolAddress((void**)&bqkv, g_bqkv);

    cudaFuncSetAttribute(attn_kernel, cudaFuncAttributeMaxDynamicSharedMemorySize,
                         ATTN_SMEM_BYTES);
    cudaFuncSetAttribute(gemm_bf16_kernel, cudaFuncAttributeMaxDynamicSharedMemorySize,
                         GEMM_SMEM_BYTES);

    const dim3 blk(256);
    const dim3 wblk(32, 8);

    // ---- weight prep (every call; deterministic) ----
    bias_concat_kernel<<<3, 1024>>>(bq, bk, bv, bqkv);
    wconv_kernel<<<dim3(32, 32), wblk>>>(Wq, wqkvh, wqkvl, D_MODEL, D_MODEL);
    wconv_kernel<<<dim3(32, 32), wblk>>>(Wk, wqkvh + (size_t)1024 * D_MODEL,
                                         wqkvl + (size_t)1024 * D_MODEL, D_MODEL, D_MODEL);
    wconv_kernel<<<dim3(32, 32), wblk>>>(Wv, wqkvh + (size_t)2048 * D_MODEL,
                                         wqkvl + (size_t)2048 * D_MODEL, D_MODEL, D_MODEL);
    wconv_kernel<<<dim3(32, 32), wblk>>>(Wo, woh, wol, D_MODEL, D_MODEL);
    wconv_kernel<<<dim3(128, 32), wblk>>>(W1, w1h, w1l, D_MODEL, DFF);
    wconv_kernel<<<dim3(32, 128), wblk>>>(W2, w2h, w2l, DFF, D_MODEL);

    // ---- transformer block ----
    ln_split_kernel<<<MROWS, blk>>>(x, g1, be1, xnh, xnl);

    gemm_bf16_kernel<<<dim3(QKV_N / 128, MROWS / 128), blk, GEMM_SMEM_BYTES>>>(
        xnh, xnl, wqkvh, wqkvl, bqkv, nullptr, qkv, nullptr, nullptr,
        MROWS, QKV_N, D_MODEL, 0);

    attn_kernel<<<dim3(S_LEN / 128, NH, BATCH), blk, ATTN_SMEM_BYTES>>>(
        qkv, qkv + 1024, qkv + 2048, ath, atl);

    gemm_bf16_kernel<<<dim3(D_MODEL / 128, MROWS / 128), blk, GEMM_SMEM_BYTES>>>(
        ath, atl, woh, wol, bo, x, h, nullptr, nullptr,
        MROWS, D_MODEL, D_MODEL, 0);

    ln_split_kernel<<<MROWS, blk>>>(h, g2, be2, hnh, hnl);

    gemm_bf16_kernel<<<dim3(DFF / 128, MROWS / 128), blk, GEMM_SMEM_BYTES>>>(
        hnh, hnl, w1h, w1l, b1, nullptr, nullptr, ffh, ffl,
        MROWS, DFF, D_MODEL, 1);

    gemm_bf16_kernel<<<dim3(D_MODEL / 128, MROWS / 128), blk, GEMM_SMEM_BYTES>>>(
        ffh, ffl, w2h, w2l, b2, h, out, nullptr, nullptr,
        MROWS, D_MODEL, DFF, 0);
}

// round 7
// speedup vs baseline: 1.6701x; 1.0186x over previous
#include <cuda_runtime.h>
#include <cuda_bf16.h>
#include <math.h>
#include <stdint.h>

// Problem constants
#define D_MODEL 1024
#define S_LEN   2048
#define BATCH   2
#define NH      16
#define DK      64
#define DFF     4096
#define MROWS   (BATCH * S_LEN)   // 4096
#define QKV_N   3072
#define QKV_PITCH 3072

typedef __nv_bfloat16 bf16;

// ---------------------------------------------------------------------------
// Scratch (device globals — no allocation allowed)
// ---------------------------------------------------------------------------
__device__ __align__(128) bf16  g_xn_h[(size_t)MROWS * D_MODEL];
__device__ __align__(128) bf16  g_xn_l[(size_t)MROWS * D_MODEL];
__device__ __align__(128) float g_qkv [(size_t)MROWS * QKV_N];
__device__ __align__(128) bf16  g_at_h[(size_t)MROWS * D_MODEL];
__device__ __align__(128) bf16  g_at_l[(size_t)MROWS * D_MODEL];
__device__ __align__(128) float g_h   [(size_t)MROWS * D_MODEL];
__device__ __align__(128) bf16  g_hn_h[(size_t)MROWS * D_MODEL];
__device__ __align__(128) bf16  g_hn_l[(size_t)MROWS * D_MODEL];
__device__ __align__(128) bf16  g_ff_h[(size_t)MROWS * DFF];
__device__ __align__(128) bf16  g_ff_l[(size_t)MROWS * DFF];
// transposed split weights: WT[n][k]
__device__ __align__(128) bf16  g_wqkvT_h[(size_t)QKV_N * D_MODEL];
__device__ __align__(128) bf16  g_wqkvT_l[(size_t)QKV_N * D_MODEL];
__device__ __align__(128) bf16  g_woT_h[(size_t)D_MODEL * D_MODEL];
__device__ __align__(128) bf16  g_woT_l[(size_t)D_MODEL * D_MODEL];
__device__ __align__(128) bf16  g_w1T_h[(size_t)DFF * D_MODEL];
__device__ __align__(128) bf16  g_w1T_l[(size_t)DFF * D_MODEL];
__device__ __align__(128) bf16  g_w2T_h[(size_t)D_MODEL * DFF];
__device__ __align__(128) bf16  g_w2T_l[(size_t)D_MODEL * DFF];
__device__ float g_bqkv[QKV_N];

__device__ __forceinline__ void split_bf16(float v, bf16& h, bf16& l) {
    h = __float2bfloat16(v);
    l = __float2bfloat16(v - __bfloat162float(h));
}

// Fast e^x on the FMA pipe (degree-4, rel err ~1e-4). Avoids MUFU bottleneck.
__device__ __forceinline__ float fast_exp(float x) {
    x = fmaxf(x, -87.0f);
    float t = fmaf(x, 1.442695041f, 12582912.0f);   // round-to-nearest magic
    float i = t - 12582912.0f;                      // rounded integer part
    float f = fmaf(x, 1.442695041f, -i);            // f in [-0.5, 0.5]
    float p = fmaf(f, 0.00898934f, 0.0558263f);
    p = fmaf(f, p, 0.2401536f);
    p = fmaf(f, p, 0.693147182f);
    p = fmaf(f, p, 1.0f);
    return p * __int_as_float(((int)i + 127) << 23);
}

// ---------------------------------------------------------------------------
// Merged weight transpose + split: all six weights in one launch.
// W[K][N] fp32 -> WT_h/WT_l [N][K] bf16
// ---------------------------------------------------------------------------
__global__ __launch_bounds__(256) void wconv_all_kernel(
    const float* __restrict__ Wq, const float* __restrict__ Wk,
    const float* __restrict__ Wv, const float* __restrict__ Wo,
    const float* __restrict__ W1, const float* __restrict__ W2,
    bf16* __restrict__ qkvh, bf16* __restrict__ qkvl,
    bf16* __restrict__ woh, bf16* __restrict__ wol,
    bf16* __restrict__ w1h, bf16* __restrict__ w1l,
    bf16* __restrict__ w2h, bf16* __restrict__ w2l)
{
    __shared__ float t[32][33];
    int b = blockIdx.x;
    const float* W; bf16 *Th, *Tl; int K, N;
    if (b < 4096) {
        int s = b >> 10; b &= 1023; K = 1024; N = 1024;
        if (s == 0)      { W = Wq; Th = qkvh; Tl = qkvl; }
        else if (s == 1) { W = Wk; Th = qkvh + (size_t)1024 * 1024;
                           Tl = qkvl + (size_t)1024 * 1024; }
        else if (s == 2) { W = Wv; Th = qkvh + (size_t)2048 * 1024;
                           Tl = qkvl + (size_t)2048 * 1024; }
        else             { W = Wo; Th = woh; Tl = wol; }
    } else if (b < 8192) {
        b -= 4096; W = W1; Th = w1h; Tl = w1l; K = 1024; N = 4096;
    } else {
        b -= 8192; W = W2; Th = w2h; Tl = w2l; K = 4096; N = 1024;
    }
    const int nb = N / 32;
    const int n0 = (b % nb) * 32, k0 = (b / nb) * 32;
    const int tx = threadIdx.x, ty = threadIdx.y;
    #pragma unroll
    for (int i = 0; i < 4; i++)
        t[ty + i * 8][tx] = W[(size_t)(k0 + ty + i * 8) * N + n0 + tx];
    __syncthreads();
    #pragma unroll
    for (int i = 0; i < 4; i++) {
        float v = t[tx][ty + i * 8];
        bf16 h, l; split_bf16(v, h, l);
        size_t o = (size_t)(n0 + ty + i * 8) * K + k0 + tx;
        Th[o] = h; Tl[o] = l;
    }
}

__global__ void bias_concat_kernel(const float* bq, const float* bk, const float* bv,
                                   float* out) {
    int i = blockIdx.x * 1024 + threadIdx.x;
    out[i] = (i < 1024) ? bq[i] : (i < 2048) ? bk[i - 1024] : bv[i - 2048];
}

// ---------------------------------------------------------------------------
// LayerNorm -> bf16 hi/lo split output
// ---------------------------------------------------------------------------
__device__ __forceinline__ float block_sum_256(float v, float* red) {
    __syncthreads();
    #pragma unroll
    for (int o = 16; o; o >>= 1) v += __shfl_xor_sync(0xffffffffu, v, o);
    if ((threadIdx.x & 31) == 0) red[threadIdx.x >> 5] = v;
    __syncthreads();
    if (threadIdx.x < 32) {
        float w = (threadIdx.x < 8) ? red[threadIdx.x] : 0.0f;
        #pragma unroll
        for (int o = 4; o; o >>= 1) w += __shfl_xor_sync(0xffffffffu, w, o);
        if (threadIdx.x == 0) red[0] = w;
    }
    __syncthreads();
    return red[0];
}

__global__ __launch_bounds__(256) void ln_split_kernel(
    const float* __restrict__ x, const float* __restrict__ g,
    const float* __restrict__ b, bf16* __restrict__ oh, bf16* __restrict__ ol)
{
    __shared__ float red[32];
    const int row = blockIdx.x;
    const int t = threadIdx.x;
    float4 v = reinterpret_cast<const float4*>(x + (size_t)row * D_MODEL)[t];

    float s = v.x + v.y + v.z + v.w;
    float mu = block_sum_256(s, red) * (1.0f / (float)D_MODEL);

    float dx = v.x - mu, dy = v.y - mu, dz = v.z - mu, dw = v.w - mu;
    float sq = dx * dx + dy * dy + dz * dz + dw * dw;
    float var = block_sum_256(sq, red) * (1.0f / (float)D_MODEL);
    float inv = rsqrtf(var + 1e-5f);

    float4 gg = reinterpret_cast<const float4*>(g)[t];
    float4 bb = reinterpret_cast<const float4*>(b)[t];
    float o0 = dx * inv * gg.x + bb.x;
    float o1 = dy * inv * gg.y + bb.y;
    float o2 = dz * inv * gg.z + bb.z;
    float o3 = dw * inv * gg.w + bb.w;

    bf16 h0, l0, h1, l1, h2, l2, h3, l3;
    split_bf16(o0, h0, l0); split_bf16(o1, h1, l1);
    split_bf16(o2, h2, l2); split_bf16(o3, h3, l3);
    size_t off = (size_t)row * D_MODEL + t * 4;
    __nv_bfloat162* ph = reinterpret_cast<__nv_bfloat162*>(oh + off);
    ph[0] = __halves2bfloat162(h0, h1);
    ph[1] = __halves2bfloat162(h2, h3);
    __nv_bfloat162* pl = reinterpret_cast<__nv_bfloat162*>(ol + off);
    pl[0] = __halves2bfloat162(l0, l1);
    pl[1] = __halves2bfloat162(l2, l3);
}

// ---------------------------------------------------------------------------
// bf16 split-precision tensor-core GEMM (mma.sync).
// C[M,N] = A[M,K]@B^T[N,K] (+bias)(+resid)(relu?), fp32 accumulate,
// 3 passes: Ah*Bh + Al*Bh + Ah*Bl (ordered for fragment-register reuse).
// 128x128x32 tiles, 256 threads (2x4 warps, 64x32 warp tiles).
// 2-stage double-buffered cp.async (load k+1 issued before compute k).
// Pitch 40 bf16 (80B rows: 16B-aligned for cp.async, conflict-free LDS).
// 80KB smem/CTA -> 2 CTAs/SM.
// ---------------------------------------------------------------------------
#define BK 32
#define APITCH 40                 // bf16 pitch (32 + 8 pad); 80B stride
#define PART_BF (128 * APITCH)    // 5120 bf16 per matrix per stage
#define STAGE_BF (4 * PART_BF)    // Ah, Al, Bh, Bl
#define STAGES 2
#define GEMM_SMEM_BYTES (STAGES * STAGE_BF * 2)   // 81920

__device__ __forceinline__ uint32_t lds32(const bf16* p) {
    return *reinterpret_cast<const uint32_t*>(p);
}

__device__ __forceinline__ void mma_bf16(float c[4], const uint32_t a[4],
                                         const uint32_t b[2]) {
    asm volatile(
        "mma.sync.aligned.m16n8k16.row.col.f32.bf16.bf16.f32 "
        "{%0,%1,%2,%3}, {%4,%5,%6,%7}, {%8,%9}, {%0,%1,%2,%3};"
        : "+f"(c[0]), "+f"(c[1]), "+f"(c[2]), "+f"(c[3])
        : "r"(a[0]), "r"(a[1]), "r"(a[2]), "r"(a[3]), "r"(b[0]), "r"(b[1]));
}

__global__ __launch_bounds__(256, 2) void gemm_bf16_kernel(
    const bf16* __restrict__ Ah, const bf16* __restrict__ Al,
    const bf16* __restrict__ Bh, const bf16* __restrict__ Bl,
    const float* __restrict__ bias, const float* __restrict__ resid,
    float* __restrict__ Cf, bf16* __restrict__ Ch, bf16* __restrict__ Cl,
    int M, int N, int K, int relu)
{
    extern __shared__ bf16 smb[];
    const int tid = threadIdx.x;
    const int lane = tid & 31;
    const int w = tid >> 5;
    const int wm = w & 1, wn = w >> 1;         // 2 x 4 warp grid
    const int g = lane >> 2, tg = lane & 3;
    const int bx = blockIdx.x, by = blockIdx.y;

    const bf16* Asrc[2] = {Ah + (size_t)(by * 128) * K, Al + (size_t)(by * 128) * K};
    const bf16* Bsrc[2] = {Bh + (size_t)(bx * 128) * K, Bl + (size_t)(bx * 128) * K};

    uint32_t smem_base = (uint32_t)__cvta_generic_to_shared(smb);

    float acc[4][4][4];
    #pragma unroll
    for (int mi = 0; mi < 4; mi++)
        #pragma unroll
        for (int ni = 0; ni < 4; ni++)
            #pragma unroll
            for (int c = 0; c < 4; c++) acc[mi][ni][c] = 0.0f;

    const int nk = K / BK;

    const int row0 = tid >> 2, seg0 = tid & 3;         // chunk tid
    const int row1 = (tid + 256) >> 2, seg1 = tid & 3; // chunk tid+256

#define LOAD_STAGE(s, k0)                                                     \
    do {                                                                      \
        uint32_t sb = smem_base + (s) * (STAGE_BF * 2);                       \
        _Pragma("unroll")                                                     \
        for (int p = 0; p < 2; p++) {                                         \
            uint32_t d0 = sb + p * (PART_BF * 2) + row0 * 80 + seg0 * 16;     \
            uint32_t d1 = sb + p * (PART_BF * 2) + row1 * 80 + seg1 * 16;     \
            const bf16* s0 = Asrc[p] + (size_t)row0 * K + (k0) + seg0 * 8;    \
            const bf16* s1 = Asrc[p] + (size_t)row1 * K + (k0) + seg1 * 8;    \
            asm volatile("cp.async.cg.shared.global [%0], [%1], 16;" ::       \
                         "r"(d0), "l"(s0));                                   \
            asm volatile("cp.async.cg.shared.global [%0], [%1], 16;" ::       \
                         "r"(d1), "l"(s1));                                   \
        }                                                                     \
        _Pragma("unroll")                                                     \
        for (int p = 0; p < 2; p++) {                                         \
            uint32_t d0 = sb + (p + 2) * (PART_BF * 2) + row0 * 80 + seg0 * 16;\
            uint32_t d1 = sb + (p + 2) * (PART_BF * 2) + row1 * 80 + seg1 * 16;\
            const bf16* s0 = Bsrc[p] + (size_t)row0 * K + (k0) + seg0 * 8;    \
            const bf16* s1 = Bsrc[p] + (size_t)row1 * K + (k0) + seg1 * 8;    \
            asm volatile("cp.async.cg.shared.global [%0], [%1], 16;" ::       \
                         "r"(d0), "l"(s0));                                   \
            asm volatile("cp.async.cg.shared.global [%0], [%1], 16;" ::       \
                         "r"(d1), "l"(s1));                                   \
        }                                                                     \
        asm volatile("cp.async.commit_group;");                               \
    } while (0)

    LOAD_STAGE(0, 0);

    for (int kt = 0; kt < nk; kt++) {
        // current stage must be fully landed
        asm volatile("cp.async.wait_group 0;" ::: "memory");
        __syncthreads();
        // issue next stage's loads into the other buffer before computing
        if (kt + 1 < nk) LOAD_STAGE((kt + 1) & 1, (kt + 1) * BK);

        const int buf = kt & 1;
        const bf16* sAh = smb + buf * STAGE_BF;
        const bf16* sAl = sAh + PART_BF;
        const bf16* sBh = sAh + 2 * PART_BF;
        const bf16* sBl = sAh + 3 * PART_BF;

        #pragma unroll
        for (int kf = 0; kf < 2; kf++) {
            const int cA = kf * 16 + tg * 2;
            uint32_t fAh[4][4], fBh[4][2];
            #pragma unroll
            for (int mi = 0; mi < 4; mi++) {
                const int r = wm * 64 + mi * 16 + g;
                fAh[mi][0] = lds32(sAh + r * APITCH + cA);
                fAh[mi][1] = lds32(sAh + (r + 8) * APITCH + cA);
                fAh[mi][2] = lds32(sAh + r * APITCH + cA + 8);
                fAh[mi][3] = lds32(sAh + (r + 8) * APITCH + cA + 8);
            }
            #pragma unroll
            for (int ni = 0; ni < 4; ni++) {
                const int r = wn * 32 + ni * 8 + g;
                fBh[ni][0] = lds32(sBh + r * APITCH + cA);
                fBh[ni][1] = lds32(sBh + r * APITCH + cA + 8);
            }
            // pass 1: Ah * Bh
            #pragma unroll
            for (int mi = 0; mi < 4; mi++)
                #pragma unroll
                for (int ni = 0; ni < 4; ni++)
                    mma_bf16(acc[mi][ni], fAh[mi], fBh[ni]);
            // pass 2: Al * Bh (reuses fBh)
            {
                uint32_t fAl[4][4];
                #pragma unroll
                for (int mi = 0; mi < 4; mi++) {
                    const int r = wm * 64 + mi * 16 + g;
                    fAl[mi][0] = lds32(sAl + r * APITCH + cA);
                    fAl[mi][1] = lds32(sAl + (r + 8) * APITCH + cA);
                    fAl[mi][2] = lds32(sAl + r * APITCH + cA + 8);
                    fAl[mi][3] = lds32(sAl + (r + 8) * APITCH + cA + 8);
                }
                #pragma unroll
                for (int mi = 0; mi < 4; mi++)
                    #pragma unroll
                    for (int ni = 0; ni < 4; ni++)
                        mma_bf16(acc[mi][ni], fAl[mi], fBh[ni]);
            }
            // pass 3: Ah * Bl (reuses fAh)
            {
                uint32_t fBl[4][2];
                #pragma unroll
                for (int ni = 0; ni < 4; ni++) {
                    const int r = wn * 32 + ni * 8 + g;
                    fBl[ni][0] = lds32(sBl + r * APITCH + cA);
                    fBl[ni][1] = lds32(sBl + r * APITCH + cA + 8);
                }
                #pragma unroll
                for (int mi = 0; mi < 4; mi++)
                    #pragma unroll
                    for (int ni = 0; ni < 4; ni++)
                        mma_bf16(acc[mi][ni], fAh[mi], fBl[ni]);
            }
        }
    }

    // epilogue
    const int bm = by * 128 + wm * 64;
    const int bn = bx * 128 + wn * 32;
    #pragma unroll
    for (int mi = 0; mi < 4; mi++) {
        #pragma unroll
        for (int ni = 0; ni < 4; ni++) {
            const int c0 = bn + ni * 8 + tg * 2;
            const float b0 = bias[c0], b1 = bias[c0 + 1];
            #pragma unroll
            for (int half = 0; half < 2; half++) {
                const int r = bm + mi * 16 + g + half * 8;
                float v0 = acc[mi][ni][half * 2 + 0] + b0;
                float v1 = acc[mi][ni][half * 2 + 1] + b1;
                if (resid) {
                    const float2 rr = *reinterpret_cast<const float2*>(
                        resid + (size_t)r * N + c0);
                    v0 += rr.x; v1 += rr.y;
                }
                if (relu) { v0 = fmaxf(v0, 0.0f); v1 = fmaxf(v1, 0.0f); }
                if (Cf) {
                    float2 o; o.x = v0; o.y = v1;
                    *reinterpret_cast<float2*>(Cf + (size_t)r * N + c0) = o;
                }
                if (Ch) {
                    bf16 h0, l0, h1, l1;
                    split_bf16(v0, h0, l0); split_bf16(v1, h1, l1);
                    *reinterpret_cast<__nv_bfloat162*>(Ch + (size_t)r * N + c0) =
                        __halves2bfloat162(h0, h1);
                    *reinterpret_cast<__nv_bfloat162*>(Cl + (size_t)r * N + c0) =
                        __halves2bfloat162(l0, l1);
                }
            }
        }
    }
}

// ---------------------------------------------------------------------------
// Causal flash attention (fp32, online softmax, fast poly exp).
// Softmax row scans split across all 256 threads (2 halves per row).
// ---------------------------------------------------------------------------
#define QST_PITCH 132
#define KST_PITCH 132
#define VS_PITCH  68
#define ST_PITCH  132
#define SM_Q_OFF  0
#define SM_KV_OFF (64 * QST_PITCH)
#define SM_ST_OFF (SM_KV_OFF + 128 * VS_PITCH)
#define SM_M_OFF  (SM_ST_OFF + 128 * ST_PITCH)
#define SM_L_OFF  (SM_M_OFF + 128)
#define SM_SC_OFF (SM_L_OFF + 128)
#define SM_PM_OFF (SM_SC_OFF + 128)
#define SM_PS_OFF (SM_PM_OFF + 256)
#define ATTN_SMEM_FLOATS (SM_PS_OFF + 256)
#define ATTN_SMEM_BYTES  (ATTN_SMEM_FLOATS * 4)

__global__ __launch_bounds__(256) void attn_kernel(
    const float* __restrict__ Q, const float* __restrict__ Kg,
    const float* __restrict__ Vg, bf16* __restrict__ Oh, bf16* __restrict__ Ol)
{
    extern __shared__ float sm[];
    float* Qst = sm + SM_Q_OFF;
    float* KV  = sm + SM_KV_OFF;
    float* St  = sm + SM_ST_OFF;
    float* m_s = sm + SM_M_OFF;
    float* l_s = sm + SM_L_OFF;
    float* sc_s = sm + SM_SC_OFF;
    float* pm_s = sm + SM_PM_OFF;
    float* ps_s = sm + SM_PS_OFF;

    const int qt = blockIdx.x, hh = blockIdx.y, bb = blockIdx.z;
    const int tid = threadIdx.x;
    const int tx = tid & 15, ty = tid >> 4;
    const int qbase = qt * 128;
    const size_t base = ((size_t)bb * S_LEN) * QKV_PITCH + (size_t)hh * DK;

    #pragma unroll
    for (int i = 0; i < 8; i++) {
        int f = tid + i * 256;
        int r = f >> 4;
        int k4 = (f & 15) * 4;
        float4 qv = *reinterpret_cast<const float4*>(
            Q + base + (size_t)(qbase + r) * QKV_PITCH + k4);
        Qst[(k4 + 0) * QST_PITCH + r] = qv.x;
        Qst[(k4 + 1) * QST_PITCH + r] = qv.y;
        Qst[(k4 + 2) * QST_PITCH + r] = qv.z;
        Qst[(k4 + 3) * QST_PITCH + r] = qv.w;
    }
    if (tid < 128) { m_s[tid] = -INFINITY; l_s[tid] = 0.0f; }

    float o[8][4];
    #pragma unroll
    for (int i = 0; i < 8; i++)
        #pragma unroll
        for (int c = 0; c < 4; c++) o[i][c] = 0.0f;

    for (int kt = 0; kt <= qt; kt++) {
        const int kbase = kt * 128;
        #pragma unroll
        for (int i = 0; i < 8; i++) {
            int f = tid + i * 256;
            int j = f >> 4;
            int k4 = (f & 15) * 4;
            float4 kv = *reinterpret_cast<const float4*>(
                Kg + base + (size_t)(kbase + j) * QKV_PITCH + k4);
            KV[(k4 + 0) * KST_PITCH + j] = kv.x;
            KV[(k4 + 1) * KST_PITCH + j] = kv.y;
            KV[(k4 + 2) * KST_PITCH + j] = kv.z;
            KV[(k4 + 3) * KST_PITCH + j] = kv.w;
        }
        __syncthreads();   // (A) Q + K ready, KV free of old V

        float s[8][8];
        #pragma unroll
        for (int i = 0; i < 8; i++)
            #pragma unroll
            for (int j = 0; j < 8; j++) s[i][j] = 0.0f;

        #pragma unroll 8
        for (int k = 0; k < DK; k++) {
            float4 q0 = *reinterpret_cast<const float4*>(&Qst[k * QST_PITCH + ty * 8]);
            float4 q1 = *reinterpret_cast<const float4*>(&Qst[k * QST_PITCH + ty * 8 + 4]);
            float qr[8] = {q0.x, q0.y, q0.z, q0.w, q1.x, q1.y, q1.z, q1.w};
            float kc[8];
            #pragma unroll
            for (int jj = 0; jj < 8; jj++)
                kc[jj] = KV[k * KST_PITCH + tx + jj * 16];
            #pragma unroll
            for (int i = 0; i < 8; i++)
                #pragma unroll
                for (int jj = 0; jj < 8; jj++)
                    s[i][jj] = fmaf(qr[i], kc[jj], s[i][jj]);
        }
        #pragma unroll
        for (int i = 0; i < 8; i++) {
            const int qi = qbase + ty * 8 + i;
            #pragma unroll
            for (int jj = 0; jj < 8; jj++) {
                const int kj = kbase + tx + jj * 16;
                float v = (kj <= qi) ? s[i][jj] * 0.125f : -1e30f;
                St[(tx + jj * 16) * ST_PITCH + ty * 8 + i] = v;
            }
        }
        __syncthreads();   // (B) St complete, K consumed -> KV reusable

        // load V tile (all 256 threads)
        #pragma unroll
        for (int i = 0; i < 8; i++) {
            int f = tid + i * 256;
            int j = f >> 4;
            int c4 = (f & 15) * 4;
            float4 vv = *reinterpret_cast<const float4*>(
                Vg + base + (size_t)(kbase + j) * QKV_PITCH + c4);
            *reinterpret_cast<float4*>(&KV[j * VS_PITCH + c4]) = vv;
        }
        // parallel softmax: thread (r, hf) owns half-row
        {
            const int r = tid & 127;
            const int hf = tid >> 7;
            const int j0 = hf * 64;
            float tmax = -INFINITY;
            #pragma unroll 4
            for (int j = j0; j < j0 + 64; j++)
                tmax = fmaxf(tmax, St[j * ST_PITCH + r]);
            pm_s[tid] = tmax;
        }
        __syncthreads();
        {
            const int r = tid & 127;
            const int hf = tid >> 7;
            const int j0 = hf * 64;
            const float nm = fmaxf(m_s[r], fmaxf(pm_s[r], pm_s[r + 128]));
            float sum = 0.0f;
            #pragma unroll 4
            for (int j = j0; j < j0 + 64; j++) {
                float p = fast_exp(St[j * ST_PITCH + r] - nm);
                St[j * ST_PITCH + r] = p;
                sum += p;
            }
            ps_s[tid] = sum;
        }
        __syncthreads();
        if (tid < 128) {
            const int r = tid;
            const float mx = m_s[r];
            const float nm = fmaxf(mx, fmaxf(pm_s[r], pm_s[r + 128]));
            const float sc = fast_exp(mx - nm);
            l_s[r] = l_s[r] * sc + ps_s[r] + ps_s[r + 128];
            m_s[r] = nm;
            sc_s[r] = sc;
        }
        __syncthreads();   // (C) P + V + scales ready

        #pragma unroll
        for (int i = 0; i < 8; i++) {
            const float sc = sc_s[ty * 8 + i];
            #pragma unroll
            for (int c = 0; c < 4; c++) o[i][c] *= sc;
        }
        #pragma unroll 4
        for (int j = 0; j < 128; j++) {
            float4 p0 = *reinterpret_cast<const float4*>(&St[j * ST_PITCH + ty * 8]);
            float4 p1 = *reinterpret_cast<const float4*>(&St[j * ST_PITCH + ty * 8 + 4]);
            float pr[8] = {p0.x, p0.y, p0.z, p0.w, p1.x, p1.y, p1.z, p1.w};
            float4 vv = *reinterpret_cast<const float4*>(&KV[j * VS_PITCH + tx * 4]);
            float vc[4] = {vv.x, vv.y, vv.z, vv.w};
            #pragma unroll
            for (int i = 0; i < 8; i++)
                #pragma unroll
                for (int c = 0; c < 4; c++)
                    o[i][c] = fmaf(pr[i], vc[c], o[i][c]);
        }
        __syncthreads();   // (D) KV/St free for next iteration
    }

    #pragma unroll
    for (int i = 0; i < 8; i++) {
        const int r = ty * 8 + i;
        const float inv = 1.0f / l_s[r];
        float v0 = o[i][0] * inv, v1 = o[i][1] * inv;
        float v2 = o[i][2] * inv, v3 = o[i][3] * inv;
        bf16 h0, l0, h1, l1, h2, l2, h3, l3;
        split_bf16(v0, h0, l0); split_bf16(v1, h1, l1);
        split_bf16(v2, h2, l2); split_bf16(v3, h3, l3);
        size_t off = ((size_t)bb * S_LEN + qbase + r) * D_MODEL + hh * DK + tx * 4;
        __nv_bfloat162* ph = reinterpret_cast<__nv_bfloat162*>(Oh + off);
        ph[0] = __halves2bfloat162(h0, h1);
        ph[1] = __halves2bfloat162(h2, h3);
        __nv_bfloat162* pl = reinterpret_cast<__nv_bfloat162*>(Ol + off);
        pl[0] = __halves2bfloat162(l0, l1);
        pl[1] = __halves2bfloat162(l2, l3);
    }
}

// ---------------------------------------------------------------------------
// kernel_launch
// Launch order matters for ncu (-s 5 -c 1 profiles launch #6 = O-proj GEMM):
// 1 wconv_all, 2 bias_concat, 3 ln1, 4 gemm_qkv, 5 attn, 6 gemm_O, ...
// ---------------------------------------------------------------------------
extern "C" void kernel_launch(void* const* d_in, const int* in_sizes, int n_in,
                              void* d_out, int out_size)
{
    const float* x   = (const float*)d_in[0];
    const float* Wq  = (const float*)d_in[2];
    const float* bq  = (const float*)d_in[3];
    const float* Wk  = (const float*)d_in[4];
    const float* bk  = (const float*)d_in[5];
    const float* Wv  = (const float*)d_in[6];
    const float* bv  = (const float*)d_in[7];
    const float* Wo  = (const float*)d_in[8];
    const float* bo  = (const float*)d_in[9];
    const float* W1  = (const float*)d_in[10];
    const float* b1  = (const float*)d_in[11];
    const float* W2  = (const float*)d_in[12];
    const float* b2  = (const float*)d_in[13];
    const float* g1  = (const float*)d_in[14];
    const float* be1 = (const float*)d_in[15];
    const float* g2  = (const float*)d_in[16];
    const float* be2 = (const float*)d_in[17];
    float* out = (float*)d_out;

    bf16 *xnh, *xnl, *ath, *atl, *hnh, *hnl, *ffh, *ffl;
    bf16 *wqkvh, *wqkvl, *woh, *wol, *w1h, *w1l, *w2h, *w2l;
    float *qkv, *h, *bqkv;
    cudaGetSymbolAddress((void**)&xnh, g_xn_h);
    cudaGetSymbolAddress((void**)&xnl, g_xn_l);
    cudaGetSymbolAddress((void**)&qkv, g_qkv);
    cudaGetSymbolAddress((void**)&ath, g_at_h);
    cudaGetSymbolAddress((void**)&atl, g_at_l);
    cudaGetSymbolAddress((void**)&h,   g_h);
    cudaGetSymbolAddress((void**)&hnh, g_hn_h);
    cudaGetSymbolAddress((void**)&hnl, g_hn_l);
    cudaGetSymbolAddress((void**)&ffh, g_ff_h);
    cudaGetSymbolAddress((void**)&ffl, g_ff_l);
    cudaGetSymbolAddress((void**)&wqkvh, g_wqkvT_h);
    cudaGetSymbolAddress((void**)&wqkvl, g_wqkvT_l);
    cudaGetSymbolAddress((void**)&woh, g_woT_h);
    cudaGetSymbolAddress((void**)&wol, g_woT_l);
    cudaGetSymbolAddress((void**)&w1h, g_w1T_h);
    cudaGetSymbolAddress((void**)&w1l, g_w1T_l);
    cudaGetSymbolAddress((void**)&w2h, g_w2T_h);
    cudaGetSymbolAddress((void**)&w2l, g_w2T_l);
    cudaGetSymbolAddress((void**)&bqkv, g_bqkv);

    cudaFuncSetAttribute(attn_kernel, cudaFuncAttributeMaxDynamicSharedMemorySize,
                         ATTN_SMEM_BYTES);
    cudaFuncSetAttribute(gemm_bf16_kernel, cudaFuncAttributeMaxDynamicSharedMemorySize,
                         GEMM_SMEM_BYTES);

    const dim3 blk(256);
    const dim3 wblk(32, 8);

    // 1: all weight transpose+split in one launch
    wconv_all_kernel<<<12288, wblk>>>(Wq, Wk, Wv, Wo, W1, W2,
                                      wqkvh, wqkvl, woh, wol,
                                      w1h, w1l, w2h, w2l);
    // 2
    bias_concat_kernel<<<3, 1024>>>(bq, bk, bv, bqkv);
    // 3
    ln_split_kernel<<<MROWS, blk>>>(x, g1, be1, xnh, xnl);
    // 4
    gemm_bf16_kernel<<<dim3(QKV_N / 128, MROWS / 128), blk, GEMM_SMEM_BYTES>>>(
        xnh, xnl, wqkvh, wqkvl, bqkv, nullptr, qkv, nullptr, nullptr,
        MROWS, QKV_N, D_MODEL, 0);
    // 5
    attn_kernel<<<dim3(S_LEN / 128, NH, BATCH), blk, ATTN_SMEM_BYTES>>>(
        qkv, qkv + 1024, qkv + 2048, ath, atl);
    // 6 (profiled by ncu -s 5 -c 1)
    gemm_bf16_kernel<<<dim3(D_MODEL / 128, MROWS / 128), blk, GEMM_SMEM_BYTES>>>(
        ath, atl, woh, wol, bo, x, h, nullptr, nullptr,
        MROWS, D_MODEL, D_MODEL, 0);
    // 7
    ln_split_kernel<<<MROWS, blk>>>(h, g2, be2, hnh, hnl);
    // 8
    gemm_bf16_kernel<<<dim3(DFF / 128, MROWS / 128), blk, GEMM_SMEM_BYTES>>>(
        hnh, hnl, w1h, w1l, b1, nullptr, nullptr, ffh, ffl,
        MROWS, DFF, D_MODEL, 1);
    // 9
    gemm_bf16_kernel<<<dim3(D_MODEL / 128, MROWS / 128), blk, GEMM_SMEM_BYTES>>>(
        ffh, ffl, w2h, w2l, b2, h, out, nullptr, nullptr,
        MROWS, D_MODEL, DFF, 0);
}

// round 8
// speedup vs baseline: 1.7930x; 1.0736x over previous
#include <cuda_runtime.h>
#include <cuda_bf16.h>
#include <math.h>
#include <stdint.h>

// Problem constants
#define D_MODEL 1024
#define S_LEN   2048
#define BATCH   2
#define NH      16
#define DK      64
#define DFF     4096
#define MROWS   (BATCH * S_LEN)   // 4096
#define QKV_N   3072
#define QKV_PITCH 3072

typedef __nv_bfloat16 bf16;

// ---------------------------------------------------------------------------
// Scratch (device globals — no allocation allowed)
// ---------------------------------------------------------------------------
__device__ __align__(128) bf16  g_xn_h[(size_t)MROWS * D_MODEL];
__device__ __align__(128) bf16  g_xn_l[(size_t)MROWS * D_MODEL];
__device__ __align__(128) float g_qkv [(size_t)MROWS * QKV_N];
__device__ __align__(128) bf16  g_at_h[(size_t)MROWS * D_MODEL];
__device__ __align__(128) bf16  g_at_l[(size_t)MROWS * D_MODEL];
__device__ __align__(128) float g_h   [(size_t)MROWS * D_MODEL];
__device__ __align__(128) bf16  g_hn_h[(size_t)MROWS * D_MODEL];
__device__ __align__(128) bf16  g_hn_l[(size_t)MROWS * D_MODEL];
__device__ __align__(128) bf16  g_ff_h[(size_t)MROWS * DFF];
__device__ __align__(128) bf16  g_ff_l[(size_t)MROWS * DFF];
// transposed split weights: WT[n][k]
__device__ __align__(128) bf16  g_wqkvT_h[(size_t)QKV_N * D_MODEL];
__device__ __align__(128) bf16  g_wqkvT_l[(size_t)QKV_N * D_MODEL];
__device__ __align__(128) bf16  g_woT_h[(size_t)D_MODEL * D_MODEL];
__device__ __align__(128) bf16  g_woT_l[(size_t)D_MODEL * D_MODEL];
__device__ __align__(128) bf16  g_w1T_h[(size_t)DFF * D_MODEL];
__device__ __align__(128) bf16  g_w1T_l[(size_t)DFF * D_MODEL];
__device__ __align__(128) bf16  g_w2T_h[(size_t)D_MODEL * DFF];
__device__ __align__(128) bf16  g_w2T_l[(size_t)D_MODEL * DFF];
__device__ float g_bqkv[QKV_N];

__device__ __forceinline__ void split_bf16(float v, bf16& h, bf16& l) {
    h = __float2bfloat16(v);
    l = __float2bfloat16(v - __bfloat162float(h));
}

// Fast e^x on the FMA pipe (degree-4, rel err ~1e-4). Avoids MUFU bottleneck.
__device__ __forceinline__ float fast_exp(float x) {
    x = fmaxf(x, -87.0f);
    float t = fmaf(x, 1.442695041f, 12582912.0f);   // round-to-nearest magic
    float i = t - 12582912.0f;                      // rounded integer part
    float f = fmaf(x, 1.442695041f, -i);            // f in [-0.5, 0.5]
    float p = fmaf(f, 0.00898934f, 0.0558263f);
    p = fmaf(f, p, 0.2401536f);
    p = fmaf(f, p, 0.693147182f);
    p = fmaf(f, p, 1.0f);
    return p * __int_as_float(((int)i + 127) << 23);
}

// ---------------------------------------------------------------------------
// Merged weight transpose + split: all six weights in one launch.
// W[K][N] fp32 -> WT_h/WT_l [N][K] bf16
// ---------------------------------------------------------------------------
__global__ __launch_bounds__(256) void wconv_all_kernel(
    const float* __restrict__ Wq, const float* __restrict__ Wk,
    const float* __restrict__ Wv, const float* __restrict__ Wo,
    const float* __restrict__ W1, const float* __restrict__ W2,
    bf16* __restrict__ qkvh, bf16* __restrict__ qkvl,
    bf16* __restrict__ woh, bf16* __restrict__ wol,
    bf16* __restrict__ w1h, bf16* __restrict__ w1l,
    bf16* __restrict__ w2h, bf16* __restrict__ w2l)
{
    __shared__ float t[32][33];
    int b = blockIdx.x;
    const float* W; bf16 *Th, *Tl; int K, N;
    if (b < 4096) {
        int s = b >> 10; b &= 1023; K = 1024; N = 1024;
        if (s == 0)      { W = Wq; Th = qkvh; Tl = qkvl; }
        else if (s == 1) { W = Wk; Th = qkvh + (size_t)1024 * 1024;
                           Tl = qkvl + (size_t)1024 * 1024; }
        else if (s == 2) { W = Wv; Th = qkvh + (size_t)2048 * 1024;
                           Tl = qkvl + (size_t)2048 * 1024; }
        else             { W = Wo; Th = woh; Tl = wol; }
    } else if (b < 8192) {
        b -= 4096; W = W1; Th = w1h; Tl = w1l; K = 1024; N = 4096;
    } else {
        b -= 8192; W = W2; Th = w2h; Tl = w2l; K = 4096; N = 1024;
    }
    const int nb = N / 32;
    const int n0 = (b % nb) * 32, k0 = (b / nb) * 32;
    const int tx = threadIdx.x, ty = threadIdx.y;
    #pragma unroll
    for (int i = 0; i < 4; i++)
        t[ty + i * 8][tx] = W[(size_t)(k0 + ty + i * 8) * N + n0 + tx];
    __syncthreads();
    #pragma unroll
    for (int i = 0; i < 4; i++) {
        float v = t[tx][ty + i * 8];
        bf16 h, l; split_bf16(v, h, l);
        size_t o = (size_t)(n0 + ty + i * 8) * K + k0 + tx;
        Th[o] = h; Tl[o] = l;
    }
}

__global__ void bias_concat_kernel(const float* bq, const float* bk, const float* bv,
                                   float* out) {
    int i = blockIdx.x * 1024 + threadIdx.x;
    out[i] = (i < 1024) ? bq[i] : (i < 2048) ? bk[i - 1024] : bv[i - 2048];
}

// ---------------------------------------------------------------------------
// LayerNorm -> bf16 hi/lo split output
// ---------------------------------------------------------------------------
__device__ __forceinline__ float block_sum_256(float v, float* red) {
    __syncthreads();
    #pragma unroll
    for (int o = 16; o; o >>= 1) v += __shfl_xor_sync(0xffffffffu, v, o);
    if ((threadIdx.x & 31) == 0) red[threadIdx.x >> 5] = v;
    __syncthreads();
    if (threadIdx.x < 32) {
        float w = (threadIdx.x < 8) ? red[threadIdx.x] : 0.0f;
        #pragma unroll
        for (int o = 4; o; o >>= 1) w += __shfl_xor_sync(0xffffffffu, w, o);
        if (threadIdx.x == 0) red[0] = w;
    }
    __syncthreads();
    return red[0];
}

__global__ __launch_bounds__(256) void ln_split_kernel(
    const float* __restrict__ x, const float* __restrict__ g,
    const float* __restrict__ b, bf16* __restrict__ oh, bf16* __restrict__ ol)
{
    __shared__ float red[32];
    const int row = blockIdx.x;
    const int t = threadIdx.x;
    float4 v = reinterpret_cast<const float4*>(x + (size_t)row * D_MODEL)[t];

    float s = v.x + v.y + v.z + v.w;
    float mu = block_sum_256(s, red) * (1.0f / (float)D_MODEL);

    float dx = v.x - mu, dy = v.y - mu, dz = v.z - mu, dw = v.w - mu;
    float sq = dx * dx + dy * dy + dz * dz + dw * dw;
    float var = block_sum_256(sq, red) * (1.0f / (float)D_MODEL);
    float inv = rsqrtf(var + 1e-5f);

    float4 gg = reinterpret_cast<const float4*>(g)[t];
    float4 bb = reinterpret_cast<const float4*>(b)[t];
    float o0 = dx * inv * gg.x + bb.x;
    float o1 = dy * inv * gg.y + bb.y;
    float o2 = dz * inv * gg.z + bb.z;
    float o3 = dw * inv * gg.w + bb.w;

    bf16 h0, l0, h1, l1, h2, l2, h3, l3;
    split_bf16(o0, h0, l0); split_bf16(o1, h1, l1);
    split_bf16(o2, h2, l2); split_bf16(o3, h3, l3);
    size_t off = (size_t)row * D_MODEL + t * 4;
    __nv_bfloat162* ph = reinterpret_cast<__nv_bfloat162*>(oh + off);
    ph[0] = __halves2bfloat162(h0, h1);
    ph[1] = __halves2bfloat162(h2, h3);
    __nv_bfloat162* pl = reinterpret_cast<__nv_bfloat162*>(ol + off);
    pl[0] = __halves2bfloat162(l0, l1);
    pl[1] = __halves2bfloat162(l2, l3);
}

// ---------------------------------------------------------------------------
// bf16 split-precision tensor-core GEMM (mma.sync).
// C[M,N] = A[M,K]@B^T[N,K] (+bias)(+resid)(relu?), fp32 accumulate,
// 3 passes: Ah*Bh + Al*Bh + Ah*Bl.
// 128x128x32 tiles, 256 threads (2x4 warps, 64x32 warp tiles).
// SMEM layout: hi|lo interleaved into 128B rows ([Ah row 64B | Al row 64B])
// with SW128 XOR swizzle (chunk ^= row&7) -> zero padding, conflict-free,
// 16B-aligned cp.async. Stage = 32KB; 3 stages = 96KB -> 2 CTAs/SM.
// Pipeline: 2 stages in flight; wait_group 1 keeps one load outstanding
// through every compute phase.
// ---------------------------------------------------------------------------
#define BK 32
#define STAGE_BYTES 32768          // (A:16KB) + (B:16KB)
#define A_HALF_BYTES 16384
#define STAGES 3
#define GEMM_SMEM_BYTES (STAGES * STAGE_BYTES)   // 98304

__device__ __forceinline__ uint32_t lds32g(const char* base, int r, int cbyte) {
    // SW128: 16B chunk index XORed with (row & 7)
    const char* p = base + r * 128 +
        ((((cbyte >> 4) ^ (r & 7)) & 7) << 4) + (cbyte & 15);
    return *reinterpret_cast<const uint32_t*>(p);
}

__device__ __forceinline__ void mma_bf16(float c[4], const uint32_t a[4],
                                         const uint32_t b[2]) {
    asm volatile(
        "mma.sync.aligned.m16n8k16.row.col.f32.bf16.bf16.f32 "
        "{%0,%1,%2,%3}, {%4,%5,%6,%7}, {%8,%9}, {%0,%1,%2,%3};"
        : "+f"(c[0]), "+f"(c[1]), "+f"(c[2]), "+f"(c[3])
        : "r"(a[0]), "r"(a[1]), "r"(a[2]), "r"(a[3]), "r"(b[0]), "r"(b[1]));
}

__global__ __launch_bounds__(256, 2) void gemm_bf16_kernel(
    const bf16* __restrict__ Ah, const bf16* __restrict__ Al,
    const bf16* __restrict__ Bh, const bf16* __restrict__ Bl,
    const float* __restrict__ bias, const float* __restrict__ resid,
    float* __restrict__ Cf, bf16* __restrict__ Ch, bf16* __restrict__ Cl,
    int M, int N, int K, int relu)
{
    extern __shared__ char smc[];
    const int tid = threadIdx.x;
    const int lane = tid & 31;
    const int w = tid >> 5;
    const int wm = w & 1, wn = w >> 1;         // 2 x 4 warp grid
    const int g = lane >> 2, tg = lane & 3;
    const int bx = blockIdx.x, by = blockIdx.y;

    const bf16* Asrc[2] = {Ah + (size_t)(by * 128) * K, Al + (size_t)(by * 128) * K};
    const bf16* Bsrc[2] = {Bh + (size_t)(bx * 128) * K, Bl + (size_t)(bx * 128) * K};

    uint32_t smem_base = (uint32_t)__cvta_generic_to_shared(smc);

    float acc[4][4][4];
    #pragma unroll
    for (int mi = 0; mi < 4; mi++)
        #pragma unroll
        for (int ni = 0; ni < 4; ni++)
            #pragma unroll
            for (int c = 0; c < 4; c++) acc[mi][ni][c] = 0.0f;

    const int nk = K / BK;

    // per-thread load mapping: 1024 16B chunks per (hi|lo) pair per stage,
    // 4 chunks per thread per pair. chunk c<4 -> hi bytes c*16, c>=4 -> lo.
#define LOAD_STAGE(s, k0)                                                     \
    do {                                                                      \
        uint32_t sb = smem_base + (s) * STAGE_BYTES;                          \
        _Pragma("unroll")                                                     \
        for (int i = 0; i < 4; i++) {                                         \
            int f = i * 256 + tid;                                            \
            int row = f >> 3, c = f & 7;                                      \
            uint32_t sw = ((uint32_t)((c ^ (row & 7)) & 7)) << 4;             \
            uint32_t dA = sb + row * 128 + sw;                                \
            uint32_t dB = dA + A_HALF_BYTES;                                  \
            const bf16* sA = Asrc[c >> 2] + (size_t)row * K + (k0) + (c & 3) * 8; \
            const bf16* sB = Bsrc[c >> 2] + (size_t)row * K + (k0) + (c & 3) * 8; \
            asm volatile("cp.async.cg.shared.global [%0], [%1], 16;" ::       \
                         "r"(dA), "l"(sA));                                   \
            asm volatile("cp.async.cg.shared.global [%0], [%1], 16;" ::       \
                         "r"(dB), "l"(sB));                                   \
        }                                                                     \
        asm volatile("cp.async.commit_group;");                               \
    } while (0)

    LOAD_STAGE(0, 0);
    LOAD_STAGE(1, BK);

    for (int kt = 0; kt < nk; kt++) {
        asm volatile("cp.async.wait_group 1;" ::: "memory");
        __syncthreads();
        // keep the pipeline 2-deep: issue stage kt+2 before computing kt
        if (kt + 2 < nk) {
            LOAD_STAGE((kt + 2) % STAGES, (kt + 2) * BK);
        } else {
            asm volatile("cp.async.commit_group;");
        }

        const char* sA = smc + (kt % STAGES) * STAGE_BYTES;
        const char* sB = sA + A_HALF_BYTES;

        #pragma unroll
        for (int kf = 0; kf < 2; kf++) {
            const int c2 = kf * 32 + tg * 4;       // byte offset in hi half
            uint32_t fAh[4][4], fBh[4][2];
            #pragma unroll
            for (int mi = 0; mi < 4; mi++) {
                const int r = wm * 64 + mi * 16 + g;
                fAh[mi][0] = lds32g(sA, r, c2);
                fAh[mi][1] = lds32g(sA, r + 8, c2);
                fAh[mi][2] = lds32g(sA, r, c2 + 16);
                fAh[mi][3] = lds32g(sA, r + 8, c2 + 16);
            }
            #pragma unroll
            for (int ni = 0; ni < 4; ni++) {
                const int r = wn * 32 + ni * 8 + g;
                fBh[ni][0] = lds32g(sB, r, c2);
                fBh[ni][1] = lds32g(sB, r, c2 + 16);
            }
            // pass 1: Ah * Bh
            #pragma unroll
            for (int mi = 0; mi < 4; mi++)
                #pragma unroll
                for (int ni = 0; ni < 4; ni++)
                    mma_bf16(acc[mi][ni], fAh[mi], fBh[ni]);
            // pass 2: Al * Bh (lo half = +64B)
            {
                uint32_t fAl[4][4];
                #pragma unroll
                for (int mi = 0; mi < 4; mi++) {
                    const int r = wm * 64 + mi * 16 + g;
                    fAl[mi][0] = lds32g(sA, r, c2 + 64);
                    fAl[mi][1] = lds32g(sA, r + 8, c2 + 64);
                    fAl[mi][2] = lds32g(sA, r, c2 + 80);
                    fAl[mi][3] = lds32g(sA, r + 8, c2 + 80);
                }
                #pragma unroll
                for (int mi = 0; mi < 4; mi++)
                    #pragma unroll
                    for (int ni = 0; ni < 4; ni++)
                        mma_bf16(acc[mi][ni], fAl[mi], fBh[ni]);
            }
            // pass 3: Ah * Bl
            {
                uint32_t fBl[4][2];
                #pragma unroll
                for (int ni = 0; ni < 4; ni++) {
                    const int r = wn * 32 + ni * 8 + g;
                    fBl[ni][0] = lds32g(sB, r, c2 + 64);
                    fBl[ni][1] = lds32g(sB, r, c2 + 80);
                }
                #pragma unroll
                for (int mi = 0; mi < 4; mi++)
                    #pragma unroll
                    for (int ni = 0; ni < 4; ni++)
                        mma_bf16(acc[mi][ni], fAh[mi], fBl[ni]);
            }
        }
    }

    // epilogue
    const int bm = by * 128 + wm * 64;
    const int bn = bx * 128 + wn * 32;
    #pragma unroll
    for (int mi = 0; mi < 4; mi++) {
        #pragma unroll
        for (int ni = 0; ni < 4; ni++) {
            const int c0 = bn + ni * 8 + tg * 2;
            const float b0 = bias[c0], b1 = bias[c0 + 1];
            #pragma unroll
            for (int half = 0; half < 2; half++) {
                const int r = bm + mi * 16 + g + half * 8;
                float v0 = acc[mi][ni][half * 2 + 0] + b0;
                float v1 = acc[mi][ni][half * 2 + 1] + b1;
                if (resid) {
                    const float2 rr = *reinterpret_cast<const float2*>(
                        resid + (size_t)r * N + c0);
                    v0 += rr.x; v1 += rr.y;
                }
                if (relu) { v0 = fmaxf(v0, 0.0f); v1 = fmaxf(v1, 0.0f); }
                if (Cf) {
                    float2 o; o.x = v0; o.y = v1;
                    *reinterpret_cast<float2*>(Cf + (size_t)r * N + c0) = o;
                }
                if (Ch) {
                    bf16 h0, l0, h1, l1;
                    split_bf16(v0, h0, l0); split_bf16(v1, h1, l1);
                    *reinterpret_cast<__nv_bfloat162*>(Ch + (size_t)r * N + c0) =
                        __halves2bfloat162(h0, h1);
                    *reinterpret_cast<__nv_bfloat162*>(Cl + (size_t)r * N + c0) =
                        __halves2bfloat162(l0, l1);
                }
            }
        }
    }
}

// ---------------------------------------------------------------------------
// Causal flash attention (fp32, online softmax, fast poly exp).
// Softmax row scans split across all 256 threads (2 halves per row).
// ---------------------------------------------------------------------------
#define QST_PITCH 132
#define KST_PITCH 132
#define VS_PITCH  68
#define ST_PITCH  132
#define SM_Q_OFF  0
#define SM_KV_OFF (64 * QST_PITCH)
#define SM_ST_OFF (SM_KV_OFF + 128 * VS_PITCH)
#define SM_M_OFF  (SM_ST_OFF + 128 * ST_PITCH)
#define SM_L_OFF  (SM_M_OFF + 128)
#define SM_SC_OFF (SM_L_OFF + 128)
#define SM_PM_OFF (SM_SC_OFF + 128)
#define SM_PS_OFF (SM_PM_OFF + 256)
#define ATTN_SMEM_FLOATS (SM_PS_OFF + 256)
#define ATTN_SMEM_BYTES  (ATTN_SMEM_FLOATS * 4)

__global__ __launch_bounds__(256) void attn_kernel(
    const float* __restrict__ Q, const float* __restrict__ Kg,
    const float* __restrict__ Vg, bf16* __restrict__ Oh, bf16* __restrict__ Ol)
{
    extern __shared__ float sm[];
    float* Qst = sm + SM_Q_OFF;
    float* KV  = sm + SM_KV_OFF;
    float* St  = sm + SM_ST_OFF;
    float* m_s = sm + SM_M_OFF;
    float* l_s = sm + SM_L_OFF;
    float* sc_s = sm + SM_SC_OFF;
    float* pm_s = sm + SM_PM_OFF;
    float* ps_s = sm + SM_PS_OFF;

    const int qt = blockIdx.x, hh = blockIdx.y, bb = blockIdx.z;
    const int tid = threadIdx.x;
    const int tx = tid & 15, ty = tid >> 4;
    const int qbase = qt * 128;
    const size_t base = ((size_t)bb * S_LEN) * QKV_PITCH + (size_t)hh * DK;

    #pragma unroll
    for (int i = 0; i < 8; i++) {
        int f = tid + i * 256;
        int r = f >> 4;
        int k4 = (f & 15) * 4;
        float4 qv = *reinterpret_cast<const float4*>(
            Q + base + (size_t)(qbase + r) * QKV_PITCH + k4);
        Qst[(k4 + 0) * QST_PITCH + r] = qv.x;
        Qst[(k4 + 1) * QST_PITCH + r] = qv.y;
        Qst[(k4 + 2) * QST_PITCH + r] = qv.z;
        Qst[(k4 + 3) * QST_PITCH + r] = qv.w;
    }
    if (tid < 128) { m_s[tid] = -INFINITY; l_s[tid] = 0.0f; }

    float o[8][4];
    #pragma unroll
    for (int i = 0; i < 8; i++)
        #pragma unroll
        for (int c = 0; c < 4; c++) o[i][c] = 0.0f;

    for (int kt = 0; kt <= qt; kt++) {
        const int kbase = kt * 128;
        #pragma unroll
        for (int i = 0; i < 8; i++) {
            int f = tid + i * 256;
            int j = f >> 4;
            int k4 = (f & 15) * 4;
            float4 kv = *reinterpret_cast<const float4*>(
                Kg + base + (size_t)(kbase + j) * QKV_PITCH + k4);
            KV[(k4 + 0) * KST_PITCH + j] = kv.x;
            KV[(k4 + 1) * KST_PITCH + j] = kv.y;
            KV[(k4 + 2) * KST_PITCH + j] = kv.z;
            KV[(k4 + 3) * KST_PITCH + j] = kv.w;
        }
        __syncthreads();   // (A) Q + K ready, KV free of old V

        float s[8][8];
        #pragma unroll
        for (int i = 0; i < 8; i++)
            #pragma unroll
            for (int j = 0; j < 8; j++) s[i][j] = 0.0f;

        #pragma unroll 8
        for (int k = 0; k < DK; k++) {
            float4 q0 = *reinterpret_cast<const float4*>(&Qst[k * QST_PITCH + ty * 8]);
            float4 q1 = *reinterpret_cast<const float4*>(&Qst[k * QST_PITCH + ty * 8 + 4]);
            float qr[8] = {q0.x, q0.y, q0.z, q0.w, q1.x, q1.y, q1.z, q1.w};
            float kc[8];
            #pragma unroll
            for (int jj = 0; jj < 8; jj++)
                kc[jj] = KV[k * KST_PITCH + tx + jj * 16];
            #pragma unroll
            for (int i = 0; i < 8; i++)
                #pragma unroll
                for (int jj = 0; jj < 8; jj++)
                    s[i][jj] = fmaf(qr[i], kc[jj], s[i][jj]);
        }
        #pragma unroll
        for (int i = 0; i < 8; i++) {
            const int qi = qbase + ty * 8 + i;
            #pragma unroll
            for (int jj = 0; jj < 8; jj++) {
                const int kj = kbase + tx + jj * 16;
                float v = (kj <= qi) ? s[i][jj] * 0.125f : -1e30f;
                St[(tx + jj * 16) * ST_PITCH + ty * 8 + i] = v;
            }
        }
        __syncthreads();   // (B) St complete, K consumed -> KV reusable

        // load V tile (all 256 threads)
        #pragma unroll
        for (int i = 0; i < 8; i++) {
            int f = tid + i * 256;
            int j = f >> 4;
            int c4 = (f & 15) * 4;
            float4 vv = *reinterpret_cast<const float4*>(
                Vg + base + (size_t)(kbase + j) * QKV_PITCH + c4);
            *reinterpret_cast<float4*>(&KV[j * VS_PITCH + c4]) = vv;
        }
        // parallel softmax: thread (r, hf) owns half-row
        {
            const int r = tid & 127;
            const int hf = tid >> 7;
            const int j0 = hf * 64;
            float tmax = -INFINITY;
            #pragma unroll 4
            for (int j = j0; j < j0 + 64; j++)
                tmax = fmaxf(tmax, St[j * ST_PITCH + r]);
            pm_s[tid] = tmax;
        }
        __syncthreads();
        {
            const int r = tid & 127;
            const int hf = tid >> 7;
            const int j0 = hf * 64;
            const float nm = fmaxf(m_s[r], fmaxf(pm_s[r], pm_s[r + 128]));
            float sum = 0.0f;
            #pragma unroll 4
            for (int j = j0; j < j0 + 64; j++) {
                float p = fast_exp(St[j * ST_PITCH + r] - nm);
                St[j * ST_PITCH + r] = p;
                sum += p;
            }
            ps_s[tid] = sum;
        }
        __syncthreads();
        if (tid < 128) {
            const int r = tid;
            const float mx = m_s[r];
            const float nm = fmaxf(mx, fmaxf(pm_s[r], pm_s[r + 128]));
            const float sc = fast_exp(mx - nm);
            l_s[r] = l_s[r] * sc + ps_s[r] + ps_s[r + 128];
            m_s[r] = nm;
            sc_s[r] = sc;
        }
        __syncthreads();   // (C) P + V + scales ready

        #pragma unroll
        for (int i = 0; i < 8; i++) {
            const float sc = sc_s[ty * 8 + i];
            #pragma unroll
            for (int c = 0; c < 4; c++) o[i][c] *= sc;
        }
        #pragma unroll 4
        for (int j = 0; j < 128; j++) {
            float4 p0 = *reinterpret_cast<const float4*>(&St[j * ST_PITCH + ty * 8]);
            float4 p1 = *reinterpret_cast<const float4*>(&St[j * ST_PITCH + ty * 8 + 4]);
            float pr[8] = {p0.x, p0.y, p0.z, p0.w, p1.x, p1.y, p1.z, p1.w};
            float4 vv = *reinterpret_cast<const float4*>(&KV[j * VS_PITCH + tx * 4]);
            float vc[4] = {vv.x, vv.y, vv.z, vv.w};
            #pragma unroll
            for (int i = 0; i < 8; i++)
                #pragma unroll
                for (int c = 0; c < 4; c++)
                    o[i][c] = fmaf(pr[i], vc[c], o[i][c]);
        }
        __syncthreads();   // (D) KV/St free for next iteration
    }

    #pragma unroll
    for (int i = 0; i < 8; i++) {
        const int r = ty * 8 + i;
        const float inv = 1.0f / l_s[r];
        float v0 = o[i][0] * inv, v1 = o[i][1] * inv;
        float v2 = o[i][2] * inv, v3 = o[i][3] * inv;
        bf16 h0, l0, h1, l1, h2, l2, h3, l3;
        split_bf16(v0, h0, l0); split_bf16(v1, h1, l1);
        split_bf16(v2, h2, l2); split_bf16(v3, h3, l3);
        size_t off = ((size_t)bb * S_LEN + qbase + r) * D_MODEL + hh * DK + tx * 4;
        __nv_bfloat162* ph = reinterpret_cast<__nv_bfloat162*>(Oh + off);
        ph[0] = __halves2bfloat162(h0, h1);
        ph[1] = __halves2bfloat162(h2, h3);
        __nv_bfloat162* pl = reinterpret_cast<__nv_bfloat162*>(Ol + off);
        pl[0] = __halves2bfloat162(l0, l1);
        pl[1] = __halves2bfloat162(l2, l3);
    }
}

// ---------------------------------------------------------------------------
// kernel_launch
// ---------------------------------------------------------------------------
extern "C" void kernel_launch(void* const* d_in, const int* in_sizes, int n_in,
                              void* d_out, int out_size)
{
    const float* x   = (const float*)d_in[0];
    const float* Wq  = (const float*)d_in[2];
    const float* bq  = (const float*)d_in[3];
    const float* Wk  = (const float*)d_in[4];
    const float* bk  = (const float*)d_in[5];
    const float* Wv  = (const float*)d_in[6];
    const float* bv  = (const float*)d_in[7];
    const float* Wo  = (const float*)d_in[8];
    const float* bo  = (const float*)d_in[9];
    const float* W1  = (const float*)d_in[10];
    const float* b1  = (const float*)d_in[11];
    const float* W2  = (const float*)d_in[12];
    const float* b2  = (const float*)d_in[13];
    const float* g1  = (const float*)d_in[14];
    const float* be1 = (const float*)d_in[15];
    const float* g2  = (const float*)d_in[16];
    const float* be2 = (const float*)d_in[17];
    float* out = (float*)d_out;

    bf16 *xnh, *xnl, *ath, *atl, *hnh, *hnl, *ffh, *ffl;
    bf16 *wqkvh, *wqkvl, *woh, *wol, *w1h, *w1l, *w2h, *w2l;
    float *qkv, *h, *bqkv;
    cudaGetSymbolAddress((void**)&xnh, g_xn_h);
    cudaGetSymbolAddress((void**)&xnl, g_xn_l);
    cudaGetSymbolAddress((void**)&qkv, g_qkv);
    cudaGetSymbolAddress((void**)&ath, g_at_h);
    cudaGetSymbolAddress((void**)&atl, g_at_l);
    cudaGetSymbolAddress((void**)&h,   g_h);
    cudaGetSymbolAddress((void**)&hnh, g_hn_h);
    cudaGetSymbolAddress((void**)&hnl, g_hn_l);
    cudaGetSymbolAddress((void**)&ffh, g_ff_h);
    cudaGetSymbolAddress((void**)&ffl, g_ff_l);
    cudaGetSymbolAddress((void**)&wqkvh, g_wqkvT_h);
    cudaGetSymbolAddress((void**)&wqkvl, g_wqkvT_l);
    cudaGetSymbolAddress((void**)&woh, g_woT_h);
    cudaGetSymbolAddress((void**)&wol, g_woT_l);
    cudaGetSymbolAddress((void**)&w1h, g_w1T_h);
    cudaGetSymbolAddress((void**)&w1l, g_w1T_l);
    cudaGetSymbolAddress((void**)&w2h, g_w2T_h);
    cudaGetSymbolAddress((void**)&w2l, g_w2T_l);
    cudaGetSymbolAddress((void**)&bqkv, g_bqkv);

    cudaFuncSetAttribute(attn_kernel, cudaFuncAttributeMaxDynamicSharedMemorySize,
                         ATTN_SMEM_BYTES);
    cudaFuncSetAttribute(gemm_bf16_kernel, cudaFuncAttributeMaxDynamicSharedMemorySize,
                         GEMM_SMEM_BYTES);

    const dim3 blk(256);
    const dim3 wblk(32, 8);

    // 1: all weight transpose+split in one launch
    wconv_all_kernel<<<12288, wblk>>>(Wq, Wk, Wv, Wo, W1, W2,
                                      wqkvh, wqkvl, woh, wol,
                                      w1h, w1l, w2h, w2l);
    // 2
    bias_concat_kernel<<<3, 1024>>>(bq, bk, bv, bqkv);
    // 3
    ln_split_kernel<<<MROWS, blk>>>(x, g1, be1, xnh, xnl);
    // 4
    gemm_bf16_kernel<<<dim3(QKV_N / 128, MROWS / 128), blk, GEMM_SMEM_BYTES>>>(
        xnh, xnl, wqkvh, wqkvl, bqkv, nullptr, qkv, nullptr, nullptr,
        MROWS, QKV_N, D_MODEL, 0);
    // 5
    attn_kernel<<<dim3(S_LEN / 128, NH, BATCH), blk, ATTN_SMEM_BYTES>>>(
        qkv, qkv + 1024, qkv + 2048, ath, atl);
    // 6 (profiled by ncu -s 5 -c 1)
    gemm_bf16_kernel<<<dim3(D_MODEL / 128, MROWS / 128), blk, GEMM_SMEM_BYTES>>>(
        ath, atl, woh, wol, bo, x, h, nullptr, nullptr,
        MROWS, D_MODEL, D_MODEL, 0);
    // 7
    ln_split_kernel<<<MROWS, blk>>>(h, g2, be2, hnh, hnl);
    // 8
    gemm_bf16_kernel<<<dim3(DFF / 128, MROWS / 128), blk, GEMM_SMEM_BYTES>>>(
        hnh, hnl, w1h, w1l, b1, nullptr, nullptr, ffh, ffl,
        MROWS, DFF, D_MODEL, 1);
    // 9
    gemm_bf16_kernel<<<dim3(D_MODEL / 128, MROWS / 128), blk, GEMM_SMEM_BYTES>>>(
        ffh, ffl, w2h, w2l, b2, h, out, nullptr, nullptr,
        MROWS, D_MODEL, DFF, 0);
}

// round 10
// speedup vs baseline: 2.1819x; 1.2168x over previous
#include <cuda_runtime.h>
#include <cuda_bf16.h>
#include <math.h>
#include <stdint.h>

// Problem constants
#define D_MODEL 1024
#define S_LEN   2048
#define BATCH   2
#define NH      16
#define DK      64
#define DFF     4096
#define MROWS   (BATCH * S_LEN)   // 4096
#define QKV_N   3072

typedef __nv_bfloat16 bf16;

// ---------------------------------------------------------------------------
// Scratch (device globals — no allocation allowed)
// ---------------------------------------------------------------------------
__device__ __align__(128) bf16  g_xn_h[(size_t)MROWS * D_MODEL];
__device__ __align__(128) bf16  g_xn_l[(size_t)MROWS * D_MODEL];
__device__ __align__(128) bf16  g_qkv_h[(size_t)MROWS * QKV_N];
__device__ __align__(128) bf16  g_qkv_l[(size_t)MROWS * QKV_N];
__device__ __align__(128) bf16  g_at_h[(size_t)MROWS * D_MODEL];
__device__ __align__(128) bf16  g_at_l[(size_t)MROWS * D_MODEL];
__device__ __align__(128) float g_h   [(size_t)MROWS * D_MODEL];
__device__ __align__(128) bf16  g_hn_h[(size_t)MROWS * D_MODEL];
__device__ __align__(128) bf16  g_hn_l[(size_t)MROWS * D_MODEL];
__device__ __align__(128) bf16  g_ff_h[(size_t)MROWS * DFF];
__device__ __align__(128) bf16  g_ff_l[(size_t)MROWS * DFF];
// transposed split weights: WT[n][k]
__device__ __align__(128) bf16  g_wqkvT_h[(size_t)QKV_N * D_MODEL];
__device__ __align__(128) bf16  g_wqkvT_l[(size_t)QKV_N * D_MODEL];
__device__ __align__(128) bf16  g_woT_h[(size_t)D_MODEL * D_MODEL];
__device__ __align__(128) bf16  g_woT_l[(size_t)D_MODEL * D_MODEL];
__device__ __align__(128) bf16  g_w1T_h[(size_t)DFF * D_MODEL];
__device__ __align__(128) bf16  g_w1T_l[(size_t)DFF * D_MODEL];
__device__ __align__(128) bf16  g_w2T_h[(size_t)D_MODEL * DFF];
__device__ __align__(128) bf16  g_w2T_l[(size_t)D_MODEL * DFF];
__device__ float g_bqkv[QKV_N];

__device__ __forceinline__ void split_bf16(float v, bf16& h, bf16& l) {
    h = __float2bfloat16(v);
    l = __float2bfloat16(v - __bfloat162float(h));
}

// Fast e^x on the FMA pipe (degree-4, rel err ~1e-4). Avoids MUFU bottleneck.
__device__ __forceinline__ float fast_exp(float x) {
    x = fmaxf(x, -87.0f);
    float t = fmaf(x, 1.442695041f, 12582912.0f);
    float i = t - 12582912.0f;
    float f = fmaf(x, 1.442695041f, -i);
    float p = fmaf(f, 0.00898934f, 0.0558263f);
    p = fmaf(f, p, 0.2401536f);
    p = fmaf(f, p, 0.693147182f);
    p = fmaf(f, p, 1.0f);
    return p * __int_as_float(((int)i + 127) << 23);
}

// ---------------------------------------------------------------------------
// Merged weight transpose + split
// ---------------------------------------------------------------------------
__global__ __launch_bounds__(256) void wconv_all_kernel(
    const float* __restrict__ Wq, const float* __restrict__ Wk,
    const float* __restrict__ Wv, const float* __restrict__ Wo,
    const float* __restrict__ W1, const float* __restrict__ W2,
    bf16* __restrict__ qkvh, bf16* __restrict__ qkvl,
    bf16* __restrict__ woh, bf16* __restrict__ wol,
    bf16* __restrict__ w1h, bf16* __restrict__ w1l,
    bf16* __restrict__ w2h, bf16* __restrict__ w2l)
{
    __shared__ float t[32][33];
    int b = blockIdx.x;
    const float* W; bf16 *Th, *Tl; int K, N;
    if (b < 4096) {
        int s = b >> 10; b &= 1023; K = 1024; N = 1024;
        if (s == 0)      { W = Wq; Th = qkvh; Tl = qkvl; }
        else if (s == 1) { W = Wk; Th = qkvh + (size_t)1024 * 1024;
                           Tl = qkvl + (size_t)1024 * 1024; }
        else if (s == 2) { W = Wv; Th = qkvh + (size_t)2048 * 1024;
                           Tl = qkvl + (size_t)2048 * 1024; }
        else             { W = Wo; Th = woh; Tl = wol; }
    } else if (b < 8192) {
        b -= 4096; W = W1; Th = w1h; Tl = w1l; K = 1024; N = 4096;
    } else {
        b -= 8192; W = W2; Th = w2h; Tl = w2l; K = 4096; N = 1024;
    }
    const int nb = N / 32;
    const int n0 = (b % nb) * 32, k0 = (b / nb) * 32;
    const int tx = threadIdx.x, ty = threadIdx.y;
    #pragma unroll
    for (int i = 0; i < 4; i++)
        t[ty + i * 8][tx] = W[(size_t)(k0 + ty + i * 8) * N + n0 + tx];
    __syncthreads();
    #pragma unroll
    for (int i = 0; i < 4; i++) {
        float v = t[tx][ty + i * 8];
        bf16 h, l; split_bf16(v, h, l);
        size_t o = (size_t)(n0 + ty + i * 8) * K + k0 + tx;
        Th[o] = h; Tl[o] = l;
    }
}

__global__ void bias_concat_kernel(const float* bq, const float* bk, const float* bv,
                                   float* out) {
    int i = blockIdx.x * 1024 + threadIdx.x;
    out[i] = (i < 1024) ? bq[i] : (i < 2048) ? bk[i - 1024] : bv[i - 2048];
}

// ---------------------------------------------------------------------------
// LayerNorm -> bf16 hi/lo split output
// ---------------------------------------------------------------------------
__device__ __forceinline__ float block_sum_256(float v, float* red) {
    __syncthreads();
    #pragma unroll
    for (int o = 16; o; o >>= 1) v += __shfl_xor_sync(0xffffffffu, v, o);
    if ((threadIdx.x & 31) == 0) red[threadIdx.x >> 5] = v;
    __syncthreads();
    if (threadIdx.x < 32) {
        float w = (threadIdx.x < 8) ? red[threadIdx.x] : 0.0f;
        #pragma unroll
        for (int o = 4; o; o >>= 1) w += __shfl_xor_sync(0xffffffffu, w, o);
        if (threadIdx.x == 0) red[0] = w;
    }
    __syncthreads();
    return red[0];
}

__global__ __launch_bounds__(256) void ln_split_kernel(
    const float* __restrict__ x, const float* __restrict__ g,
    const float* __restrict__ b, bf16* __restrict__ oh, bf16* __restrict__ ol)
{
    __shared__ float red[32];
    const int row = blockIdx.x;
    const int t = threadIdx.x;
    float4 v = reinterpret_cast<const float4*>(x + (size_t)row * D_MODEL)[t];

    float s = v.x + v.y + v.z + v.w;
    float mu = block_sum_256(s, red) * (1.0f / (float)D_MODEL);

    float dx = v.x - mu, dy = v.y - mu, dz = v.z - mu, dw = v.w - mu;
    float sq = dx * dx + dy * dy + dz * dz + dw * dw;
    float var = block_sum_256(sq, red) * (1.0f / (float)D_MODEL);
    float inv = rsqrtf(var + 1e-5f);

    float4 gg = reinterpret_cast<const float4*>(g)[t];
    float4 bb = reinterpret_cast<const float4*>(b)[t];
    float o0 = dx * inv * gg.x + bb.x;
    float o1 = dy * inv * gg.y + bb.y;
    float o2 = dz * inv * gg.z + bb.z;
    float o3 = dw * inv * gg.w + bb.w;

    bf16 h0, l0, h1, l1, h2, l2, h3, l3;
    split_bf16(o0, h0, l0); split_bf16(o1, h1, l1);
    split_bf16(o2, h2, l2); split_bf16(o3, h3, l3);
    size_t off = (size_t)row * D_MODEL + t * 4;
    __nv_bfloat162* ph = reinterpret_cast<__nv_bfloat162*>(oh + off);
    ph[0] = __halves2bfloat162(h0, h1);
    ph[1] = __halves2bfloat162(h2, h3);
    __nv_bfloat162* pl = reinterpret_cast<__nv_bfloat162*>(ol + off);
    pl[0] = __halves2bfloat162(l0, l1);
    pl[1] = __halves2bfloat162(l2, l3);
}

// ---------------------------------------------------------------------------
// Shared GEMM building blocks (SW128 swizzle, lds32, mma)
// ---------------------------------------------------------------------------
__device__ __forceinline__ uint32_t lds32g(const char* base, int r, int cbyte) {
    const char* p = base + r * 128 +
        ((((cbyte >> 4) ^ (r & 7)) & 7) << 4) + (cbyte & 15);
    return *reinterpret_cast<const uint32_t*>(p);
}

__device__ __forceinline__ void mma_bf16(float c[4], const uint32_t a[4],
                                         const uint32_t b[2]) {
    asm volatile(
        "mma.sync.aligned.m16n8k16.row.col.f32.bf16.bf16.f32 "
        "{%0,%1,%2,%3}, {%4,%5,%6,%7}, {%8,%9}, {%0,%1,%2,%3};"
        : "+f"(c[0]), "+f"(c[1]), "+f"(c[2]), "+f"(c[3])
        : "r"(a[0]), "r"(a[1]), "r"(a[2]), "r"(a[3]), "r"(b[0]), "r"(b[1]));
}

// ---------------------------------------------------------------------------
// bf16 split-precision tensor-core GEMM.
// ---------------------------------------------------------------------------
#define BK 32
#define STAGE_BYTES 32768
#define A_HALF_BYTES 16384
#define STAGES 3
#define GEMM_SMEM_BYTES (STAGES * STAGE_BYTES)   // 98304

__global__ __launch_bounds__(256, 2) void gemm_bf16_kernel(
    const bf16* __restrict__ Ah, const bf16* __restrict__ Al,
    const bf16* __restrict__ Bh, const bf16* __restrict__ Bl,
    const float* __restrict__ bias, const float* __restrict__ resid,
    float* __restrict__ Cf, bf16* __restrict__ Ch, bf16* __restrict__ Cl,
    int M, int N, int K, int relu)
{
    extern __shared__ char smc[];
    const int tid = threadIdx.x;
    const int lane = tid & 31;
    const int w = tid >> 5;
    const int wm = w & 1, wn = w >> 1;
    const int g = lane >> 2, tg = lane & 3;
    const int bx = blockIdx.x, by = blockIdx.y;

    const bf16* Asrc[2] = {Ah + (size_t)(by * 128) * K, Al + (size_t)(by * 128) * K};
    const bf16* Bsrc[2] = {Bh + (size_t)(bx * 128) * K, Bl + (size_t)(bx * 128) * K};

    uint32_t smem_base = (uint32_t)__cvta_generic_to_shared(smc);

    float acc[4][4][4];
    #pragma unroll
    for (int mi = 0; mi < 4; mi++)
        #pragma unroll
        for (int ni = 0; ni < 4; ni++)
            #pragma unroll
            for (int c = 0; c < 4; c++) acc[mi][ni][c] = 0.0f;

    const int nk = K / BK;

#define LOAD_STAGE(s, k0)                                                     \
    do {                                                                      \
        uint32_t sb = smem_base + (s) * STAGE_BYTES;                          \
        _Pragma("unroll")                                                     \
        for (int i = 0; i < 4; i++) {                                         \
            int f = i * 256 + tid;                                            \
            int row = f >> 3, c = f & 7;                                      \
            uint32_t sw = ((uint32_t)((c ^ (row & 7)) & 7)) << 4;             \
            uint32_t dA = sb + row * 128 + sw;                                \
            uint32_t dB = dA + A_HALF_BYTES;                                  \
            const bf16* sA = Asrc[c >> 2] + (size_t)row * K + (k0) + (c & 3) * 8; \
            const bf16* sB = Bsrc[c >> 2] + (size_t)row * K + (k0) + (c & 3) * 8; \
            asm volatile("cp.async.cg.shared.global [%0], [%1], 16;" ::       \
                         "r"(dA), "l"(sA));                                   \
            asm volatile("cp.async.cg.shared.global [%0], [%1], 16;" ::       \
                         "r"(dB), "l"(sB));                                   \
        }                                                                     \
        asm volatile("cp.async.commit_group;");                               \
    } while (0)

    LOAD_STAGE(0, 0);
    LOAD_STAGE(1, BK);

    for (int kt = 0; kt < nk; kt++) {
        asm volatile("cp.async.wait_group 1;" ::: "memory");
        __syncthreads();
        if (kt + 2 < nk) {
            LOAD_STAGE((kt + 2) % STAGES, (kt + 2) * BK);
        } else {
            asm volatile("cp.async.commit_group;");
        }

        const char* sA = smc + (kt % STAGES) * STAGE_BYTES;
        const char* sB = sA + A_HALF_BYTES;

        #pragma unroll
        for (int kf = 0; kf < 2; kf++) {
            const int c2 = kf * 32 + tg * 4;
            uint32_t fAh[4][4], fBh[4][2];
            #pragma unroll
            for (int mi = 0; mi < 4; mi++) {
                const int r = wm * 64 + mi * 16 + g;
                fAh[mi][0] = lds32g(sA, r, c2);
                fAh[mi][1] = lds32g(sA, r + 8, c2);
                fAh[mi][2] = lds32g(sA, r, c2 + 16);
                fAh[mi][3] = lds32g(sA, r + 8, c2 + 16);
            }
            #pragma unroll
            for (int ni = 0; ni < 4; ni++) {
                const int r = wn * 32 + ni * 8 + g;
                fBh[ni][0] = lds32g(sB, r, c2);
                fBh[ni][1] = lds32g(sB, r, c2 + 16);
            }
            #pragma unroll
            for (int mi = 0; mi < 4; mi++)
                #pragma unroll
                for (int ni = 0; ni < 4; ni++)
                    mma_bf16(acc[mi][ni], fAh[mi], fBh[ni]);
            {
                uint32_t fAl[4][4];
                #pragma unroll
                for (int mi = 0; mi < 4; mi++) {
                    const int r = wm * 64 + mi * 16 + g;
                    fAl[mi][0] = lds32g(sA, r, c2 + 64);
                    fAl[mi][1] = lds32g(sA, r + 8, c2 + 64);
                    fAl[mi][2] = lds32g(sA, r, c2 + 80);
                    fAl[mi][3] = lds32g(sA, r + 8, c2 + 80);
                }
                #pragma unroll
                for (int mi = 0; mi < 4; mi++)
                    #pragma unroll
                    for (int ni = 0; ni < 4; ni++)
                        mma_bf16(acc[mi][ni], fAl[mi], fBh[ni]);
            }
            {
                uint32_t fBl[4][2];
                #pragma unroll
                for (int ni = 0; ni < 4; ni++) {
                    const int r = wn * 32 + ni * 8 + g;
                    fBl[ni][0] = lds32g(sB, r, c2 + 64);
                    fBl[ni][1] = lds32g(sB, r, c2 + 80);
                }
                #pragma unroll
                for (int mi = 0; mi < 4; mi++)
                    #pragma unroll
                    for (int ni = 0; ni < 4; ni++)
                        mma_bf16(acc[mi][ni], fAh[mi], fBl[ni]);
            }
        }
    }

    const int bm = by * 128 + wm * 64;
    const int bn = bx * 128 + wn * 32;
    #pragma unroll
    for (int mi = 0; mi < 4; mi++) {
        #pragma unroll
        for (int ni = 0; ni < 4; ni++) {
            const int c0 = bn + ni * 8 + tg * 2;
            const float b0 = bias[c0], b1 = bias[c0 + 1];
            #pragma unroll
            for (int half = 0; half < 2; half++) {
                const int r = bm + mi * 16 + g + half * 8;
                float v0 = acc[mi][ni][half * 2 + 0] + b0;
                float v1 = acc[mi][ni][half * 2 + 1] + b1;
                if (resid) {
                    const float2 rr = *reinterpret_cast<const float2*>(
                        resid + (size_t)r * N + c0);
                    v0 += rr.x; v1 += rr.y;
                }
                if (relu) { v0 = fmaxf(v0, 0.0f); v1 = fmaxf(v1, 0.0f); }
                if (Cf) {
                    float2 o; o.x = v0; o.y = v1;
                    *reinterpret_cast<float2*>(Cf + (size_t)r * N + c0) = o;
                }
                if (Ch) {
                    bf16 h0, l0, h1, l1;
                    split_bf16(v0, h0, l0); split_bf16(v1, h1, l1);
                    *reinterpret_cast<__nv_bfloat162*>(Ch + (size_t)r * N + c0) =
                        __halves2bfloat162(h0, h1);
                    *reinterpret_cast<__nv_bfloat162*>(Cl + (size_t)r * N + c0) =
                        __halves2bfloat162(l0, l1);
                }
            }
        }
    }
}

// ---------------------------------------------------------------------------
// Causal flash attention via mma.sync bf16 hi/lo.
// Block = 128 q rows x head x batch, 256 threads (8 warps).
// QK^T: warps 2(wm q64) x 4(wn k32); 3 passes QhKh+QlKh+QhKl.
// Softmax fp32 in regs (fast_exp), row reduce via shfl(tg) + smem over wn.
// P split exactly to bf16 hi/lo, stored to smem in GEMM A-layout.
// V transposed to smem (B-layout, c-major over j) during K load.
// PV: warps 4(wq q32) x 2(wc c32); 3 passes PhVh+PlVh+PhVl; online O in regs.
// ---------------------------------------------------------------------------
#define AT_Q_OFF   0        // 2 chunks x 16KB = 32KB
#define AT_K_OFF   32768    // 2 chunks x 16KB
#define AT_VT_OFF  65536    // 4 chunks x 8KB (64 rows x 128B)
#define AT_P_OFF   98304    // 4 chunks x 16KB
#define AT_RED_OFF 163840
// reductions: m[128] l[128] sc[128] nm[128] pmax[4*128] psum[4*128]
#define ATTN_SMEM_BYTES (AT_RED_OFF + 1536 * 4)   // 169984

#define SWZ(r, b) (((((b) >> 4) ^ ((r) & 7)) & 7) << 4 | ((b) & 15))

__global__ __launch_bounds__(256, 1) void attn_mma_kernel(
    const bf16* __restrict__ QKVh, const bf16* __restrict__ QKVl,
    bf16* __restrict__ Oh, bf16* __restrict__ Ol)
{
    extern __shared__ char smc[];
    float* red  = reinterpret_cast<float*>(smc + AT_RED_OFF);
    float* m_s  = red;
    float* l_s  = red + 128;
    float* sc_s = red + 256;
    float* nm_s = red + 384;
    float* pmax = red + 512;    // [4][128]
    float* psum = red + 1024;   // [4][128]

    const int qt = blockIdx.x, hh = blockIdx.y, bb = blockIdx.z;
    const int tid = threadIdx.x;
    const int lane = tid & 31;
    const int w = tid >> 5;
    const int g = lane >> 2, tg = lane & 3;
    const int wm = w & 1, wn = w >> 1;     // QK mapping
    const int wq = w & 3, wc = w >> 2;     // PV mapping
    const int qbase = qt * 128;
    const int grow0 = bb * S_LEN + qbase;  // global q row base
    uint32_t smem_base = (uint32_t)__cvta_generic_to_shared(smc);

    // cp.async load of a 128row x 32k hi/lo tile into A-layout
#define AT_LOAD_TILE(dstoff, rbase, colbase)                                  \
    do {                                                                      \
        _Pragma("unroll")                                                     \
        for (int i = 0; i < 4; i++) {                                         \
            int f = i * 256 + tid;                                            \
            int row = f >> 3, c = f & 7;                                      \
            uint32_t dst = smem_base + (dstoff) + row * 128 +                 \
                           (((uint32_t)((c ^ (row & 7)) & 7)) << 4);          \
            const bf16* src = ((c < 4) ? QKVh : QKVl) +                       \
                (size_t)((rbase) + row) * QKV_N + (colbase) + (c & 3) * 8;    \
            asm volatile("cp.async.cg.shared.global [%0], [%1], 16;" ::       \
                         "r"(dst), "l"(src));                                 \
        }                                                                     \
    } while (0)

    // Q tiles (2 chunks)
    AT_LOAD_TILE(AT_Q_OFF, grow0, hh * 64);
    AT_LOAD_TILE(AT_Q_OFF + 16384, grow0, hh * 64 + 32);
    asm volatile("cp.async.commit_group;");

    if (tid < 128) { m_s[tid] = -INFINITY; l_s[tid] = 0.0f; }

    float o[2][4][4];
    #pragma unroll
    for (int mi = 0; mi < 2; mi++)
        #pragma unroll
        for (int ni = 0; ni < 4; ni++)
            #pragma unroll
            for (int c = 0; c < 4; c++) o[mi][ni][c] = 0.0f;

    for (int kt = 0; kt <= qt; kt++) {
        const int kbase = kt * 128;
        const int krow0 = bb * S_LEN + kbase;

        // K tiles (2 chunks)
        AT_LOAD_TILE(AT_K_OFF, krow0, 1024 + hh * 64);
        AT_LOAD_TILE(AT_K_OFF + 16384, krow0, 1024 + hh * 64 + 32);
        asm volatile("cp.async.commit_group;");

        // V transpose: V[j][c] -> Vt[c][j] hi/lo (B-layout, 4 j-chunks)
        {
            const int cg = (tid & 15) * 4;
            const int j0 = tid >> 4;
            #pragma unroll
            for (int jj = 0; jj < 8; jj++) {
                const int j = j0 + jj * 16;
                const size_t goff = (size_t)(krow0 + j) * QKV_N + 2048 +
                                    hh * 64 + cg;
                unsigned long long vh =
                    *reinterpret_cast<const unsigned long long*>(QKVh + goff);
                unsigned long long vl =
                    *reinterpret_cast<const unsigned long long*>(QKVl + goff);
                const int cbase = AT_VT_OFF + (j >> 5) * 8192;
                const int bh = (j & 31) * 2;
                #pragma unroll
                for (int u = 0; u < 4; u++) {
                    const int c = cg + u;
                    unsigned short eh = (unsigned short)(vh >> (16 * u));
                    unsigned short el = (unsigned short)(vl >> (16 * u));
                    *reinterpret_cast<unsigned short*>(
                        smc + cbase + c * 128 + SWZ(c, bh)) = eh;
                    *reinterpret_cast<unsigned short*>(
                        smc + cbase + c * 128 + SWZ(c, bh + 64)) = el;
                }
            }
        }

        asm volatile("cp.async.wait_group 0;" ::: "memory");
        __syncthreads();   // (1) Q,K,Vt ready; prev-tile P/Vt consumers done

        // ---- QK^T ----
        float acc[4][4][4];
        #pragma unroll
        for (int mi = 0; mi < 4; mi++)
            #pragma unroll
            for (int ni = 0; ni < 4; ni++)
                #pragma unroll
                for (int c = 0; c < 4; c++) acc[mi][ni][c] = 0.0f;

        #pragma unroll
        for (int ck = 0; ck < 2; ck++) {
            const char* sQ = smc + AT_Q_OFF + ck * 16384;
            const char* sK = smc + AT_K_OFF + ck * 16384;
            #pragma unroll
            for (int kf = 0; kf < 2; kf++) {
                const int c2 = kf * 32 + tg * 4;
                uint32_t fAh[4][4], fBh[4][2];
                #pragma unroll
                for (int mi = 0; mi < 4; mi++) {
                    const int r = wm * 64 + mi * 16 + g;
                    fAh[mi][0] = lds32g(sQ, r, c2);
                    fAh[mi][1] = lds32g(sQ, r + 8, c2);
                    fAh[mi][2] = lds32g(sQ, r, c2 + 16);
                    fAh[mi][3] = lds32g(sQ, r + 8, c2 + 16);
                }
                #pragma unroll
                for (int ni = 0; ni < 4; ni++) {
                    const int r = wn * 32 + ni * 8 + g;
                    fBh[ni][0] = lds32g(sK, r, c2);
                    fBh[ni][1] = lds32g(sK, r, c2 + 16);
                }
                #pragma unroll
                for (int mi = 0; mi < 4; mi++)
                    #pragma unroll
                    for (int ni = 0; ni < 4; ni++)
                        mma_bf16(acc[mi][ni], fAh[mi], fBh[ni]);
                {
                    uint32_t fAl[4][4];
                    #pragma unroll
                    for (int mi = 0; mi < 4; mi++) {
                        const int r = wm * 64 + mi * 16 + g;
                        fAl[mi][0] = lds32g(sQ, r, c2 + 64);
                        fAl[mi][1] = lds32g(sQ, r + 8, c2 + 64);
                        fAl[mi][2] = lds32g(sQ, r, c2 + 80);
                        fAl[mi][3] = lds32g(sQ, r + 8, c2 + 80);
                    }
                    #pragma unroll
                    for (int mi = 0; mi < 4; mi++)
                        #pragma unroll
                        for (int ni = 0; ni < 4; ni++)
                            mma_bf16(acc[mi][ni], fAl[mi], fBh[ni]);
                }
                {
                    uint32_t fBl[4][2];
                    #pragma unroll
                    for (int ni = 0; ni < 4; ni++) {
                        const int r = wn * 32 + ni * 8 + g;
                        fBl[ni][0] = lds32g(sK, r, c2 + 64);
                        fBl[ni][1] = lds32g(sK, r, c2 + 80);
                    }
                    #pragma unroll
                    for (int mi = 0; mi < 4; mi++)
                        #pragma unroll
                        for (int ni = 0; ni < 4; ni++)
                            mma_bf16(acc[mi][ni], fAh[mi], fBl[ni]);
                }
            }
        }

        // ---- scale + causal mask ----
        #pragma unroll
        for (int mi = 0; mi < 4; mi++) {
            const int qi0 = qbase + wm * 64 + mi * 16 + g;
            #pragma unroll
            for (int ni = 0; ni < 4; ni++) {
                const int kj = kbase + wn * 32 + ni * 8 + tg * 2;
                acc[mi][ni][0] = (kj     <= qi0) ? acc[mi][ni][0] * 0.125f : -1e30f;
                acc[mi][ni][1] = (kj + 1 <= qi0) ? acc[mi][ni][1] * 0.125f : -1e30f;
                acc[mi][ni][2] = (kj     <= qi0 + 8) ? acc[mi][ni][2] * 0.125f : -1e30f;
                acc[mi][ni][3] = (kj + 1 <= qi0 + 8) ? acc[mi][ni][3] * 0.125f : -1e30f;
            }
        }

        // ---- row max: shfl over tg + smem over wn ----
        #pragma unroll
        for (int mi = 0; mi < 4; mi++) {
            float m0 = -INFINITY, m1 = -INFINITY;
            #pragma unroll
            for (int ni = 0; ni < 4; ni++) {
                m0 = fmaxf(m0, fmaxf(acc[mi][ni][0], acc[mi][ni][1]));
                m1 = fmaxf(m1, fmaxf(acc[mi][ni][2], acc[mi][ni][3]));
            }
            m0 = fmaxf(m0, __shfl_xor_sync(0xffffffffu, m0, 1));
            m0 = fmaxf(m0, __shfl_xor_sync(0xffffffffu, m0, 2));
            m1 = fmaxf(m1, __shfl_xor_sync(0xffffffffu, m1, 1));
            m1 = fmaxf(m1, __shfl_xor_sync(0xffffffffu, m1, 2));
            if (tg == 0) {
                const int r = wm * 64 + mi * 16 + g;
                pmax[wn * 128 + r] = m0;
                pmax[wn * 128 + r + 8] = m1;
            }
        }
        __syncthreads();   // (2)
        if (tid < 128) {
            float nm = m_s[tid];
            #pragma unroll
            for (int wi = 0; wi < 4; wi++) nm = fmaxf(nm, pmax[wi * 128 + tid]);
            sc_s[tid] = fast_exp(m_s[tid] - nm);
            nm_s[tid] = nm;
            m_s[tid] = nm;
        }
        __syncthreads();   // (3)

        // ---- exp, P split + store, row sums ----
        #pragma unroll
        for (int mi = 0; mi < 4; mi++) {
            const int r0 = wm * 64 + mi * 16 + g;
            const int r1 = r0 + 8;
            const float nm0 = nm_s[r0], nm1 = nm_s[r1];
            float s0 = 0.0f, s1 = 0.0f;
            const int pb0 = AT_P_OFF + wn * 16384 + r0 * 128;
            const int pb1 = AT_P_OFF + wn * 16384 + r1 * 128;
            #pragma unroll
            for (int ni = 0; ni < 4; ni++) {
                float p00 = fast_exp(acc[mi][ni][0] - nm0);
                float p01 = fast_exp(acc[mi][ni][1] - nm0);
                float p10 = fast_exp(acc[mi][ni][2] - nm1);
                float p11 = fast_exp(acc[mi][ni][3] - nm1);
                s0 += p00 + p01;
                s1 += p10 + p11;
                const int bh = ni * 16 + tg * 4;
                bf16 h0, l0, h1, l1;
                split_bf16(p00, h0, l0); split_bf16(p01, h1, l1);
                *reinterpret_cast<__nv_bfloat162*>(smc + pb0 + SWZ(r0, bh)) =
                    __halves2bfloat162(h0, h1);
                *reinterpret_cast<__nv_bfloat162*>(smc + pb0 + SWZ(r0, bh + 64)) =
                    __halves2bfloat162(l0, l1);
                split_bf16(p10, h0, l0); split_bf16(p11, h1, l1);
                *reinterpret_cast<__nv_bfloat162*>(smc + pb1 + SWZ(r1, bh)) =
                    __halves2bfloat162(h0, h1);
                *reinterpret_cast<__nv_bfloat162*>(smc + pb1 + SWZ(r1, bh + 64)) =
                    __halves2bfloat162(l0, l1);
            }
            s0 += __shfl_xor_sync(0xffffffffu, s0, 1);
            s0 += __shfl_xor_sync(0xffffffffu, s0, 2);
            s1 += __shfl_xor_sync(0xffffffffu, s1, 1);
            s1 += __shfl_xor_sync(0xffffffffu, s1, 2);
            if (tg == 0) {
                psum[wn * 128 + r0] = s0;
                psum[wn * 128 + r1] = s1;
            }
        }
        __syncthreads();   // (4) P + psum ready
        if (tid < 128) {
            l_s[tid] = l_s[tid] * sc_s[tid] +
                psum[tid] + psum[128 + tid] + psum[256 + tid] + psum[384 + tid];
        }

        // ---- rescale O, then PV ----
        #pragma unroll
        for (int mi = 0; mi < 2; mi++) {
            const int r0 = wq * 32 + mi * 16 + g;
            const float sc0 = sc_s[r0], sc1 = sc_s[r0 + 8];
            #pragma unroll
            for (int ni = 0; ni < 4; ni++) {
                o[mi][ni][0] *= sc0; o[mi][ni][1] *= sc0;
                o[mi][ni][2] *= sc1; o[mi][ni][3] *= sc1;
            }
        }
        #pragma unroll
        for (int cj = 0; cj < 4; cj++) {
            const char* sP = smc + AT_P_OFF + cj * 16384;
            const char* sV = smc + AT_VT_OFF + cj * 8192;
            #pragma unroll
            for (int kf = 0; kf < 2; kf++) {
                const int c2 = kf * 32 + tg * 4;
                uint32_t fPh[2][4], fVh[4][2];
                #pragma unroll
                for (int mi = 0; mi < 2; mi++) {
                    const int r = wq * 32 + mi * 16 + g;
                    fPh[mi][0] = lds32g(sP, r, c2);
                    fPh[mi][1] = lds32g(sP, r + 8, c2);
                    fPh[mi][2] = lds32g(sP, r, c2 + 16);
                    fPh[mi][3] = lds32g(sP, r + 8, c2 + 16);
                }
                #pragma unroll
                for (int ni = 0; ni < 4; ni++) {
                    const int r = wc * 32 + ni * 8 + g;
                    fVh[ni][0] = lds32g(sV, r, c2);
                    fVh[ni][1] = lds32g(sV, r, c2 + 16);
                }
                #pragma unroll
                for (int mi = 0; mi < 2; mi++)
                    #pragma unroll
                    for (int ni = 0; ni < 4; ni++)
                        mma_bf16(o[mi][ni], fPh[mi], fVh[ni]);
                {
                    uint32_t fPl[2][4];
                    #pragma unroll
                    for (int mi = 0; mi < 2; mi++) {
                        const int r = wq * 32 + mi * 16 + g;
                        fPl[mi][0] = lds32g(sP, r, c2 + 64);
                        fPl[mi][1] = lds32g(sP, r + 8, c2 + 64);
                        fPl[mi][2] = lds32g(sP, r, c2 + 80);
                        fPl[mi][3] = lds32g(sP, r + 8, c2 + 80);
                    }
                    #pragma unroll
                    for (int mi = 0; mi < 2; mi++)
                        #pragma unroll
                        for (int ni = 0; ni < 4; ni++)
                            mma_bf16(o[mi][ni], fPl[mi], fVh[ni]);
                }
                {
                    uint32_t fVl[4][2];
                    #pragma unroll
                    for (int ni = 0; ni < 4; ni++) {
                        const int r = wc * 32 + ni * 8 + g;
                        fVl[ni][0] = lds32g(sV, r, c2 + 64);
                        fVl[ni][1] = lds32g(sV, r, c2 + 80);
                    }
                    #pragma unroll
                    for (int mi = 0; mi < 2; mi++)
                        #pragma unroll
                        for (int ni = 0; ni < 4; ni++)
                            mma_bf16(o[mi][ni], fPh[mi], fVl[ni]);
                }
            }
        }
        __syncthreads();   // (5) tile done; smem reusable
    }

    // ---- output: o / l -> bf16 hi/lo ----
    #pragma unroll
    for (int mi = 0; mi < 2; mi++) {
        #pragma unroll
        for (int half = 0; half < 2; half++) {
            const int r = wq * 32 + mi * 16 + g + half * 8;
            const float inv = 1.0f / l_s[r];
            const size_t grow = (size_t)(grow0 + r) * D_MODEL +
                                hh * 64 + wc * 32 + tg * 2;
            #pragma unroll
            for (int ni = 0; ni < 4; ni++) {
                float v0 = o[mi][ni][half * 2 + 0] * inv;
                float v1 = o[mi][ni][half * 2 + 1] * inv;
                bf16 h0, l0, h1, l1;
                split_bf16(v0, h0, l0); split_bf16(v1, h1, l1);
                *reinterpret_cast<__nv_bfloat162*>(Oh + grow + ni * 8) =
                    __halves2bfloat162(h0, h1);
                *reinterpret_cast<__nv_bfloat162*>(Ol + grow + ni * 8) =
                    __halves2bfloat162(l0, l1);
            }
        }
    }
}

// ---------------------------------------------------------------------------
// kernel_launch
// Launch order (ncu -s 5 -c 1 profiles launch #6 = O-proj GEMM):
// 1 wconv_all, 2 bias_concat, 3 ln1, 4 gemm_qkv, 5 attn, 6 gemm_O, ...
// ---------------------------------------------------------------------------
extern "C" void kernel_launch(void* const* d_in, const int* in_sizes, int n_in,
                              void* d_out, int out_size)
{
    const float* x   = (const float*)d_in[0];
    const float* Wq  = (const float*)d_in[2];
    const float* bq  = (const float*)d_in[3];
    const float* Wk  = (const float*)d_in[4];
    const float* bk  = (const float*)d_in[5];
    const float* Wv  = (const float*)d_in[6];
    const float* bv  = (const float*)d_in[7];
    const float* Wo  = (const float*)d_in[8];
    const float* bo  = (const float*)d_in[9];
    const float* W1  = (const float*)d_in[10];
    const float* b1  = (const float*)d_in[11];
    const float* W2  = (const float*)d_in[12];
    const float* b2  = (const float*)d_in[13];
    const float* g1  = (const float*)d_in[14];
    const float* be1 = (const float*)d_in[15];
    const float* g2  = (const float*)d_in[16];
    const float* be2 = (const float*)d_in[17];
    float* out = (float*)d_out;

    bf16 *xnh, *xnl, *qkvh, *qkvl, *ath, *atl, *hnh, *hnl, *ffh, *ffl;
    bf16 *wqkvh, *wqkvl, *woh, *wol, *w1h, *w1l, *w2h, *w2l;
    float *h, *bqkv;
    cudaGetSymbolAddress((void**)&xnh, g_xn_h);
    cudaGetSymbolAddress((void**)&xnl, g_xn_l);
    cudaGetSymbolAddress((void**)&qkvh, g_qkv_h);
    cudaGetSymbolAddress((void**)&qkvl, g_qkv_l);
    cudaGetSymbolAddress((void**)&ath, g_at_h);
    cudaGetSymbolAddress((void**)&atl, g_at_l);
    cudaGetSymbolAddress((void**)&h,   g_h);
    cudaGetSymbolAddress((void**)&hnh, g_hn_h);
    cudaGetSymbolAddress((void**)&hnl, g_hn_l);
    cudaGetSymbolAddress((void**)&ffh, g_ff_h);
    cudaGetSymbolAddress((void**)&ffl, g_ff_l);
    cudaGetSymbolAddress((void**)&wqkvh, g_wqkvT_h);
    cudaGetSymbolAddress((void**)&wqkvl, g_wqkvT_l);
    cudaGetSymbolAddress((void**)&woh, g_woT_h);
    cudaGetSymbolAddress((void**)&wol, g_woT_l);
    cudaGetSymbolAddress((void**)&w1h, g_w1T_h);
    cudaGetSymbolAddress((void**)&w1l, g_w1T_l);
    cudaGetSymbolAddress((void**)&w2h, g_w2T_h);
    cudaGetSymbolAddress((void**)&w2l, g_w2T_l);
    cudaGetSymbolAddress((void**)&bqkv, g_bqkv);

    cudaFuncSetAttribute(attn_mma_kernel, cudaFuncAttributeMaxDynamicSharedMemorySize,
                         ATTN_SMEM_BYTES);
    cudaFuncSetAttribute(gemm_bf16_kernel, cudaFuncAttributeMaxDynamicSharedMemorySize,
                         GEMM_SMEM_BYTES);

    const dim3 blk(256);
    const dim3 wblk(32, 8);

    // 1
    wconv_all_kernel<<<12288, wblk>>>(Wq, Wk, Wv, Wo, W1, W2,
                                      wqkvh, wqkvl, woh, wol,
                                      w1h, w1l, w2h, w2l);
    // 2
    bias_concat_kernel<<<3, 1024>>>(bq, bk, bv, bqkv);
    // 3
    ln_split_kernel<<<MROWS, blk>>>(x, g1, be1, xnh, xnl);
    // 4: QKV projection -> bf16 hi/lo
    gemm_bf16_kernel<<<dim3(QKV_N / 128, MROWS / 128), blk, GEMM_SMEM_BYTES>>>(
        xnh, xnl, wqkvh, wqkvl, bqkv, nullptr, nullptr, qkvh, qkvl,
        MROWS, QKV_N, D_MODEL, 0);
    // 5: tensor-core attention
    attn_mma_kernel<<<dim3(S_LEN / 128, NH, BATCH), blk, ATTN_SMEM_BYTES>>>(
        qkvh, qkvl, ath, atl);
    // 6 (profiled)
    gemm_bf16_kernel<<<dim3(D_MODEL / 128, MROWS / 128), blk, GEMM_SMEM_BYTES>>>(
        ath, atl, woh, wol, bo, x, h, nullptr, nullptr,
        MROWS, D_MODEL, D_MODEL, 0);
    // 7
    ln_split_kernel<<<MROWS, blk>>>(h, g2, be2, hnh, hnl);
    // 8
    gemm_bf16_kernel<<<dim3(DFF / 128, MROWS / 128), blk, GEMM_SMEM_BYTES>>>(
        hnh, hnl, w1h, w1l, b1, nullptr, nullptr, ffh, ffl,
        MROWS, DFF, D_MODEL, 1);
    // 9
    gemm_bf16_kernel<<<dim3(D_MODEL / 128, MROWS / 128), blk, GEMM_SMEM_BYTES>>>(
        ffh, ffl, w2h, w2l, b2, h, out, nullptr, nullptr,
        MROWS, D_MODEL, DFF, 0);
}